// round 2
// baseline (speedup 1.0000x reference)
#include <cuda_runtime.h>
#include <math.h>

// ---------------------------------------------------------------------------
// Problem constants (fixed shapes)
// ---------------------------------------------------------------------------
namespace {
constexpr int cB  = 2;
constexpr int cS  = 2048;
constexpr int cH  = 4096;
constexpr int cNH = 32;
constexpr int cHD = 128;
constexpr int cM  = cB * cS;      // 4096 rows (b*s)
constexpr int cQKVN = 3 * cH;     // 12288

// GEMM tiling
constexpr int BM = 128, BN = 128, BK = 8, TM = 8, TN = 8;  // 256 threads

// Attention tiling
constexpr int BQ = 64, BKT = 64;
constexpr int SD = cHD + 4;       // padded row stride for Q/K/V smem
constexpr int PD = BKT + 4;       // padded row stride for P smem
}

// ---------------------------------------------------------------------------
// Scratch (allocation-free rule: __device__ globals)
// ---------------------------------------------------------------------------
__device__ float g_q[(size_t)cB * cNH * cS * cHD];
__device__ float g_k[(size_t)cB * cNH * cS * cHD];
__device__ float g_v[(size_t)cB * cNH * cS * cHD];
__device__ float g_ctx[(size_t)cM * cH];

// ---------------------------------------------------------------------------
// Kernel 1: QKV GEMM.  C[m,o] = sum_h A[m,h]*W[o,h] + b[o]
// A: [4096, 4096] row-major (hidden), W: [12288, 4096] row-major.
// Epilogue scatters into g_q/g_k/g_v with layout [b][nh][s][d].
// Since BN == 128 == HD, each block column maps to one (nh, t) pair:
//   nh = blockIdx.x / 3, t = blockIdx.x % 3.
// ---------------------------------------------------------------------------
__global__ __launch_bounds__(256) void sgemm_qkv(
    const float* __restrict__ A,
    const float* __restrict__ W,
    const float* __restrict__ bias)
{
    __shared__ float As[BK][BM];
    __shared__ float Bs[BK][BN];

    const int bm  = blockIdx.y * BM;
    const int bn  = blockIdx.x * BN;
    const int tid = threadIdx.x;
    const int lr  = tid >> 1;            // 0..127 (row in tile)
    const int lc  = (tid & 1) << 2;      // 0 or 4 (k-offset)
    const int ty  = tid >> 4;            // 0..15
    const int tx  = tid & 15;            // 0..15

    const float* Ap = A + (size_t)(bm + lr) * cH + lc;
    const float* Wp = W + (size_t)(bn + lr) * cH + lc;

    float acc[TM][TN];
#pragma unroll
    for (int i = 0; i < TM; i++)
#pragma unroll
        for (int j = 0; j < TN; j++) acc[i][j] = 0.f;

    for (int k0 = 0; k0 < cH; k0 += BK) {
        float4 a4 = *(const float4*)(Ap + k0);
        float4 b4 = *(const float4*)(Wp + k0);
        As[lc + 0][lr] = a4.x; As[lc + 1][lr] = a4.y;
        As[lc + 2][lr] = a4.z; As[lc + 3][lr] = a4.w;
        Bs[lc + 0][lr] = b4.x; Bs[lc + 1][lr] = b4.y;
        Bs[lc + 2][lr] = b4.z; Bs[lc + 3][lr] = b4.w;
        __syncthreads();
#pragma unroll
        for (int kk = 0; kk < BK; kk++) {
            float a[TM], b[TN];
#pragma unroll
            for (int i = 0; i < TM; i++) a[i] = As[kk][ty * TM + i];
#pragma unroll
            for (int j = 0; j < TN; j++) b[j] = Bs[kk][tx * TN + j];
#pragma unroll
            for (int i = 0; i < TM; i++)
#pragma unroll
                for (int j = 0; j < TN; j++)
                    acc[i][j] = fmaf(a[i], b[j], acc[i][j]);
        }
        __syncthreads();
    }

    // Scatter epilogue
    const int nh = blockIdx.x / 3;
    const int t  = blockIdx.x % 3;
    float* dst = (t == 0) ? g_q : (t == 1) ? g_k : g_v;
#pragma unroll
    for (int i = 0; i < TM; i++) {
        const int m = bm + ty * TM + i;
        const int b = m / cS;
        const int s = m % cS;
        const size_t base = ((size_t)(b * cNH + nh) * cS + s) * cHD;
#pragma unroll
        for (int j = 0; j < TN; j++) {
            const int d = tx * TN + j;
            dst[base + d] = acc[i][j] + bias[bn + d];
        }
    }
}

// ---------------------------------------------------------------------------
// Kernel 2: causal flash attention with alibi.
// grid: (S/BQ, B*NH), block: 256 threads (16x16 logical).
// Each thread owns rows ty*4..ty*4+3; score cols {tx + 16*j}; out cols tx*8..+7.
// ---------------------------------------------------------------------------
__global__ __launch_bounds__(256) void attn_kernel(const float* __restrict__ alibi)
{
    extern __shared__ float smem[];
    float* Qs = smem;                      // [BQ][SD]
    float* Ks = Qs + BQ * SD;              // [BKT][SD]
    float* Vs = Ks + BKT * SD;             // [BKT][SD]
    float* Ps = Vs + BKT * SD;             // [BQ][PD]
    float* mS = Ps + BQ * PD;              // [BQ]
    float* lS = mS + BQ;                   // [BQ]

    const int qi  = blockIdx.x;
    const int bh  = blockIdx.y;
    const int b   = bh / cNH;
    const int nh  = bh % cNH;
    const int tid = threadIdx.x;
    const int ty  = tid >> 4;
    const int tx  = tid & 15;
    const size_t headbase = (size_t)bh * cS * cHD;
    const float inv_norm = 0.08838834764831845f;   // 1/sqrt(128)

    // Load Q tile
    for (int i = tid; i < BQ * (cHD / 4); i += 256) {
        const int row = i / (cHD / 4);
        const int c4  = i % (cHD / 4);
        float4 v = *(const float4*)&g_q[headbase + (size_t)(qi * BQ + row) * cHD + c4 * 4];
        *(float4*)&Qs[row * SD + c4 * 4] = v;
    }
    if (tid < BQ) { mS[tid] = -INFINITY; lS[tid] = 0.f; }

    float o_acc[4][8];
#pragma unroll
    for (int i = 0; i < 4; i++)
#pragma unroll
        for (int j = 0; j < 8; j++) o_acc[i][j] = 0.f;

    __syncthreads();

    for (int kt = 0; kt <= qi; kt++) {
        // Load K/V tiles
        for (int i = tid; i < BKT * (cHD / 4); i += 256) {
            const int row = i / (cHD / 4);
            const int c4  = i % (cHD / 4);
            const size_t src = headbase + (size_t)(kt * BKT + row) * cHD + c4 * 4;
            *(float4*)&Ks[row * SD + c4 * 4] = *(const float4*)&g_k[src];
            *(float4*)&Vs[row * SD + c4 * 4] = *(const float4*)&g_v[src];
        }
        __syncthreads();

        // Scores: s[i][j] for rows ty*4+i, cols tx + 16*j
        float s[4][4];
#pragma unroll
        for (int i = 0; i < 4; i++)
#pragma unroll
            for (int j = 0; j < 4; j++) s[i][j] = 0.f;

        for (int d = 0; d < cHD; d += 4) {
            float4 qv[4], kv[4];
#pragma unroll
            for (int i = 0; i < 4; i++)
                qv[i] = *(const float4*)&Qs[(ty * 4 + i) * SD + d];
#pragma unroll
            for (int j = 0; j < 4; j++)
                kv[j] = *(const float4*)&Ks[(tx + 16 * j) * SD + d];
#pragma unroll
            for (int i = 0; i < 4; i++)
#pragma unroll
                for (int j = 0; j < 4; j++) {
                    s[i][j] = fmaf(qv[i].x, kv[j].x, s[i][j]);
                    s[i][j] = fmaf(qv[i].y, kv[j].y, s[i][j]);
                    s[i][j] = fmaf(qv[i].z, kv[j].z, s[i][j]);
                    s[i][j] = fmaf(qv[i].w, kv[j].w, s[i][j]);
                }
        }

        // alibi + mask
        int   kg[4];
        float al[4];
#pragma unroll
        for (int j = 0; j < 4; j++) {
            kg[j] = kt * BKT + tx + 16 * j;
            al[j] = alibi[(size_t)bh * cS + kg[j]];
        }
#pragma unroll
        for (int i = 0; i < 4; i++) {
            const int qg = qi * BQ + ty * 4 + i;
#pragma unroll
            for (int j = 0; j < 4; j++) {
                float sc = s[i][j] * inv_norm + al[j];
                s[i][j] = (kg[j] > qg) ? -100000.0f : sc;
            }
        }

        // Online softmax: reduce over the 16 lanes owning this row's columns
        float mloc[4];
#pragma unroll
        for (int i = 0; i < 4; i++) {
            mloc[i] = fmaxf(fmaxf(s[i][0], s[i][1]), fmaxf(s[i][2], s[i][3]));
#pragma unroll
            for (int off = 8; off >= 1; off >>= 1)
                mloc[i] = fmaxf(mloc[i], __shfl_xor_sync(0xffffffffu, mloc[i], off, 16));
        }

        float m_new[4], scl[4], lloc[4];
#pragma unroll
        for (int i = 0; i < 4; i++) {
            const int r = ty * 4 + i;
            const float m_old = mS[r];
            m_new[i] = fmaxf(m_old, mloc[i]);
            scl[i]   = __expf(m_old - m_new[i]);
            lloc[i]  = 0.f;
#pragma unroll
            for (int j = 0; j < 4; j++) {
                const float p = __expf(s[i][j] - m_new[i]);
                Ps[r * PD + tx + 16 * j] = p;
                lloc[i] += p;
            }
#pragma unroll
            for (int off = 8; off >= 1; off >>= 1)
                lloc[i] += __shfl_xor_sync(0xffffffffu, lloc[i], off, 16);
        }
        if (tx == 0) {
#pragma unroll
            for (int i = 0; i < 4; i++) {
                const int r = ty * 4 + i;
                mS[r] = m_new[i];
                lS[r] = lS[r] * scl[i] + lloc[i];
            }
        }
        __syncthreads();

        // O update: rescale and accumulate P @ V
#pragma unroll
        for (int i = 0; i < 4; i++)
#pragma unroll
            for (int j = 0; j < 8; j++) o_acc[i][j] *= scl[i];

        for (int kk = 0; kk < BKT; kk++) {
            float p[4];
#pragma unroll
            for (int i = 0; i < 4; i++) p[i] = Ps[(ty * 4 + i) * PD + kk];
            const float4 v0 = *(const float4*)&Vs[kk * SD + tx * 8];
            const float4 v1 = *(const float4*)&Vs[kk * SD + tx * 8 + 4];
#pragma unroll
            for (int i = 0; i < 4; i++) {
                o_acc[i][0] = fmaf(p[i], v0.x, o_acc[i][0]);
                o_acc[i][1] = fmaf(p[i], v0.y, o_acc[i][1]);
                o_acc[i][2] = fmaf(p[i], v0.z, o_acc[i][2]);
                o_acc[i][3] = fmaf(p[i], v0.w, o_acc[i][3]);
                o_acc[i][4] = fmaf(p[i], v1.x, o_acc[i][4]);
                o_acc[i][5] = fmaf(p[i], v1.y, o_acc[i][5]);
                o_acc[i][6] = fmaf(p[i], v1.z, o_acc[i][6]);
                o_acc[i][7] = fmaf(p[i], v1.w, o_acc[i][7]);
            }
        }
        __syncthreads();
    }

    // Final normalize + write ctx [b][s][h], h = nh*HD + d
#pragma unroll
    for (int i = 0; i < 4; i++) {
        const int r = ty * 4 + i;
        const float inv_l = 1.0f / lS[r];
        const int qg = qi * BQ + r;
        const size_t base = (size_t)(b * cS + qg) * cH + nh * cHD + tx * 8;
#pragma unroll
        for (int j = 0; j < 8; j++)
            g_ctx[base + j] = o_acc[i][j] * inv_l;
    }
}

// ---------------------------------------------------------------------------
// Kernel 3: dense GEMM + bias + residual -> out
// out[m,o] = residual[m,o] + sum_h ctx[m,h]*Wd[o,h] + bd[o]
// ---------------------------------------------------------------------------
__global__ __launch_bounds__(256) void sgemm_dense(
    const float* __restrict__ W,
    const float* __restrict__ bias,
    const float* __restrict__ residual,
    float* __restrict__ out)
{
    __shared__ float As[BK][BM];
    __shared__ float Bs[BK][BN];

    const int bm  = blockIdx.y * BM;
    const int bn  = blockIdx.x * BN;
    const int tid = threadIdx.x;
    const int lr  = tid >> 1;
    const int lc  = (tid & 1) << 2;
    const int ty  = tid >> 4;
    const int tx  = tid & 15;

    const float* Ap = g_ctx + (size_t)(bm + lr) * cH + lc;
    const float* Wp = W + (size_t)(bn + lr) * cH + lc;

    float acc[TM][TN];
#pragma unroll
    for (int i = 0; i < TM; i++)
#pragma unroll
        for (int j = 0; j < TN; j++) acc[i][j] = 0.f;

    for (int k0 = 0; k0 < cH; k0 += BK) {
        float4 a4 = *(const float4*)(Ap + k0);
        float4 b4 = *(const float4*)(Wp + k0);
        As[lc + 0][lr] = a4.x; As[lc + 1][lr] = a4.y;
        As[lc + 2][lr] = a4.z; As[lc + 3][lr] = a4.w;
        Bs[lc + 0][lr] = b4.x; Bs[lc + 1][lr] = b4.y;
        Bs[lc + 2][lr] = b4.z; Bs[lc + 3][lr] = b4.w;
        __syncthreads();
#pragma unroll
        for (int kk = 0; kk < BK; kk++) {
            float a[TM], b[TN];
#pragma unroll
            for (int i = 0; i < TM; i++) a[i] = As[kk][ty * TM + i];
#pragma unroll
            for (int j = 0; j < TN; j++) b[j] = Bs[kk][tx * TN + j];
#pragma unroll
            for (int i = 0; i < TM; i++)
#pragma unroll
                for (int j = 0; j < TN; j++)
                    acc[i][j] = fmaf(a[i], b[j], acc[i][j]);
        }
        __syncthreads();
    }

#pragma unroll
    for (int i = 0; i < TM; i++) {
        const int m = bm + ty * TM + i;
#pragma unroll
        for (int j = 0; j < TN; j++) {
            const int o = bn + tx * TN + j;
            const size_t idx = (size_t)m * cH + o;
            out[idx] = acc[i][j] + bias[o] + residual[idx];
        }
    }
}

// ---------------------------------------------------------------------------
// Launch
// ---------------------------------------------------------------------------
extern "C" void kernel_launch(void* const* d_in, const int* in_sizes, int n_in,
                              void* d_out, int out_size)
{
    (void)in_sizes; (void)n_in; (void)out_size;
    const float* hidden   = (const float*)d_in[0];
    const float* residual = (const float*)d_in[1];
    const float* alibi    = (const float*)d_in[2];
    // d_in[3] attention_mask: pure causal, not read
    const float* W_qkv    = (const float*)d_in[4];
    const float* b_qkv    = (const float*)d_in[5];
    const float* W_dense  = (const float*)d_in[6];
    const float* b_dense  = (const float*)d_in[7];
    float* out = (float*)d_out;

    // 1) QKV GEMM -> scattered q/k/v
    dim3 g1(cQKVN / BN, cM / BM);          // (96, 32)
    sgemm_qkv<<<g1, 256>>>(hidden, W_qkv, b_qkv);

    // 2) attention -> g_ctx
    const size_t attn_smem =
        (size_t)(3 * BQ * SD + BQ * PD + 2 * BQ) * sizeof(float);  // ~119 KB
    cudaFuncSetAttribute(attn_kernel,
                         cudaFuncAttributeMaxDynamicSharedMemorySize,
                         (int)attn_smem);
    attn_kernel<<<dim3(cS / BQ, cB * cNH), 256, attn_smem>>>(alibi);

    // 3) dense GEMM + residual -> out
    dim3 g3(cH / BN, cM / BM);             // (32, 32)
    sgemm_dense<<<g3, 256>>>(W_dense, b_dense, residual, out);
}

// round 4
// speedup vs baseline: 2.2663x; 2.2663x over previous
#include <cuda_runtime.h>
#include <cuda_bf16.h>
#include <math.h>
#include <cstdint>

// ---------------------------------------------------------------------------
// Problem constants
// ---------------------------------------------------------------------------
namespace {
constexpr int cB  = 2;
constexpr int cS  = 2048;
constexpr int cH  = 4096;
constexpr int cNH = 32;
constexpr int cHD = 128;
constexpr int cM  = cB * cS;      // 4096
constexpr int cQKVN = 3 * cH;     // 12288

// Attention tiling
constexpr int BQ = 64, BKT = 64;
constexpr int SD = cHD + 4;
constexpr int PD = BKT + 4;

// Tensor GEMM tiling (mma.sync path)
constexpr int GBM = 128, GBN = 128, GBK = 32;
constexpr int SKB   = 80;                 // smem row stride bytes (32 bf16 + 8 pad)
constexpr int TILEB = GBM * SKB;          // 10240 bytes per tile
constexpr int STAGEB = 4 * TILEB;         // Ahi,Alo,Bhi,Blo = 40960
constexpr int GEMM_SMEM = 2 * STAGEB;     // 81920
}

// ---------------------------------------------------------------------------
// Scratch (__device__ globals; allocation-free rule)
// ---------------------------------------------------------------------------
__device__ float g_q[(size_t)cB * cNH * cS * cHD];
__device__ float g_k[(size_t)cB * cNH * cS * cHD];
__device__ float g_v[(size_t)cB * cNH * cS * cHD];

__device__ __nv_bfloat16 g_hid_hi[(size_t)cM * cH];
__device__ __nv_bfloat16 g_hid_lo[(size_t)cM * cH];
__device__ __nv_bfloat16 g_wqkv_hi[(size_t)cQKVN * cH];
__device__ __nv_bfloat16 g_wqkv_lo[(size_t)cQKVN * cH];
__device__ __nv_bfloat16 g_wd_hi[(size_t)cH * cH];
__device__ __nv_bfloat16 g_wd_lo[(size_t)cH * cH];
__device__ __nv_bfloat16 g_ctx_hi[(size_t)cM * cH];
__device__ __nv_bfloat16 g_ctx_lo[(size_t)cM * cH];

// ---------------------------------------------------------------------------
// PTX helpers — ONLY non-arch-specific instructions (sm_80+ class):
// mma.sync bf16, ldmatrix, cp.async. No tcgen05/TMEM/TMA.
// ---------------------------------------------------------------------------
__device__ __forceinline__ uint32_t smem_u32(const void* p) {
    uint32_t a;
    asm("{ .reg .u64 t; cvta.to.shared.u64 t, %1; cvt.u32.u64 %0, t; }" : "=r"(a) : "l"(p));
    return a;
}
__device__ __forceinline__ void mma_bf16(float* c, const uint32_t* a, const uint32_t* b) {
    asm volatile(
        "mma.sync.aligned.m16n8k16.row.col.f32.bf16.bf16.f32 "
        "{%0,%1,%2,%3}, {%4,%5,%6,%7}, {%8,%9}, {%0,%1,%2,%3};"
        : "+f"(c[0]), "+f"(c[1]), "+f"(c[2]), "+f"(c[3])
        : "r"(a[0]), "r"(a[1]), "r"(a[2]), "r"(a[3]), "r"(b[0]), "r"(b[1]));
}
__device__ __forceinline__ void ldsm_x4(uint32_t* r, uint32_t addr) {
    asm volatile("ldmatrix.sync.aligned.m8n8.x4.shared.b16 {%0,%1,%2,%3}, [%4];"
                 : "=r"(r[0]), "=r"(r[1]), "=r"(r[2]), "=r"(r[3]) : "r"(addr));
}
__device__ __forceinline__ void ldsm_x2(uint32_t* r, uint32_t addr) {
    asm volatile("ldmatrix.sync.aligned.m8n8.x2.shared.b16 {%0,%1}, [%2];"
                 : "=r"(r[0]), "=r"(r[1]) : "r"(addr));
}
__device__ __forceinline__ void cp_async16(uint32_t s, const void* g) {
    asm volatile("cp.async.cg.shared.global [%0], [%1], 16;" :: "r"(s), "l"(g));
}
#define CP_COMMIT() asm volatile("cp.async.commit_group;" ::: "memory")
#define CP_WAIT(n)  asm volatile("cp.async.wait_group %0;" :: "n"(n) : "memory")

// ---------------------------------------------------------------------------
// fp32 -> (bf16 hi, bf16 lo) split
// ---------------------------------------------------------------------------
__global__ __launch_bounds__(256) void split_fp32(
    const float4* __restrict__ src,
    __nv_bfloat162* __restrict__ hi,
    __nv_bfloat162* __restrict__ lo)
{
    const size_t i = (size_t)blockIdx.x * 256 + threadIdx.x;
    const float4 v = src[i];
    __nv_bfloat16 hx = __float2bfloat16_rn(v.x);
    __nv_bfloat16 hy = __float2bfloat16_rn(v.y);
    __nv_bfloat16 hz = __float2bfloat16_rn(v.z);
    __nv_bfloat16 hw = __float2bfloat16_rn(v.w);
    __nv_bfloat16 lx = __float2bfloat16_rn(v.x - __bfloat162float(hx));
    __nv_bfloat16 ly = __float2bfloat16_rn(v.y - __bfloat162float(hy));
    __nv_bfloat16 lz = __float2bfloat16_rn(v.z - __bfloat162float(hz));
    __nv_bfloat16 lw = __float2bfloat16_rn(v.w - __bfloat162float(hw));
    hi[2 * i]     = __nv_bfloat162(hx, hy);
    hi[2 * i + 1] = __nv_bfloat162(hz, hw);
    lo[2 * i]     = __nv_bfloat162(lx, ly);
    lo[2 * i + 1] = __nv_bfloat162(lz, lw);
}

// ---------------------------------------------------------------------------
// Tensor-core GEMM via mma.sync: C[m,o] = sum_k A[m,k]*B[o,k]
// 3-term bf16 split: Ah*Bh + Ah*Bl + Al*Bh, fp32 accumulate.
// 8 warps: warp (wm, wn) in 2x4; warp tile 64x32; 4x4 m16n8k16 tiles.
// MODE 0: QKV scatter into g_q/g_k/g_v (+bias). MODE 1: out = acc+bias+residual.
// ---------------------------------------------------------------------------
template <int MODE>
__global__ __launch_bounds__(256, 2) void tc_gemm(
    const __nv_bfloat16* __restrict__ Ahi, const __nv_bfloat16* __restrict__ Alo,
    const __nv_bfloat16* __restrict__ Bhi, const __nv_bfloat16* __restrict__ Blo,
    const float* __restrict__ bias,
    const float* __restrict__ residual,
    float* __restrict__ out)
{
    extern __shared__ char smem[];
    const uint32_t sbase = smem_u32(smem);
    const int tid  = threadIdx.x;
    const int wid  = tid >> 5;
    const int lane = tid & 31;
    const int wm   = wid >> 2;          // 0..1
    const int wn   = wid & 3;           // 0..3
    const int bm   = blockIdx.y * GBM;
    const int bn   = blockIdx.x * GBN;

    const __nv_bfloat16* Ah = Ahi + (size_t)bm * cH;
    const __nv_bfloat16* Al = Alo + (size_t)bm * cH;
    const __nv_bfloat16* Bh = Bhi + (size_t)bn * cH;
    const __nv_bfloat16* Bl = Blo + (size_t)bn * cH;

    float acc[4][4][4];
#pragma unroll
    for (int mi = 0; mi < 4; mi++)
#pragma unroll
        for (int nj = 0; nj < 4; nj++)
#pragma unroll
            for (int r = 0; r < 4; r++) acc[mi][nj][r] = 0.f;

    // ldmatrix lane address components
    const int aRow = ((lane >> 3) & 1) * 8 + (lane & 7);  // row within 16
    const int aK   = (lane >> 4) * 8;                     // 0 or 8
    const int bl15 = lane & 15;
    const int bN   = bl15 & 7;                            // n within 8
    const int bK   = (bl15 >> 3) * 8;                     // 0 or 8

    // chunk loader: 4 tiles of 128x32 bf16, 16B cp.async each
    auto load_chunk = [&](uint32_t stage, int k0) {
#pragma unroll
        for (int it = 0; it < 2; ++it) {
            const int c   = tid + it * 256;     // 0..511
            const int row = c >> 2;
            const int kc  = c & 3;
            const uint32_t so = (uint32_t)(row * SKB + kc * 16);
            const size_t  go  = (size_t)row * cH + k0 + kc * 8;
            cp_async16(stage + 0 * TILEB + so, Ah + go);
            cp_async16(stage + 1 * TILEB + so, Al + go);
            cp_async16(stage + 2 * TILEB + so, Bh + go);
            cp_async16(stage + 3 * TILEB + so, Bl + go);
        }
    };

    constexpr int NCH = cH / GBK;   // 128
    load_chunk(sbase, 0);
    CP_COMMIT();

    for (int ch = 0; ch < NCH; ++ch) {
        if (ch + 1 < NCH) {
            load_chunk(sbase + ((ch + 1) & 1) * STAGEB, (ch + 1) * GBK);
            CP_COMMIT();
            CP_WAIT(1);
        } else {
            CP_WAIT(0);
        }
        __syncthreads();

        const uint32_t st = sbase + (ch & 1) * STAGEB;
#pragma unroll
        for (int ks = 0; ks < 2; ++ks) {
            uint32_t ah[4][4], al[4][4];
#pragma unroll
            for (int mi = 0; mi < 4; ++mi) {
                const uint32_t ao =
                    (uint32_t)((wm * 64 + mi * 16 + aRow) * SKB + (ks * 16 + aK) * 2);
                ldsm_x4(ah[mi], st + 0 * TILEB + ao);
                ldsm_x4(al[mi], st + 1 * TILEB + ao);
            }
#pragma unroll
            for (int nj = 0; nj < 4; ++nj) {
                const uint32_t bo =
                    (uint32_t)((wn * 32 + nj * 8 + bN) * SKB + (ks * 16 + bK) * 2);
                uint32_t bh[2], bl[2];
                ldsm_x2(bh, st + 2 * TILEB + bo);
                ldsm_x2(bl, st + 3 * TILEB + bo);
#pragma unroll
                for (int mi = 0; mi < 4; ++mi) {
                    mma_bf16(acc[mi][nj], ah[mi], bh);
                    mma_bf16(acc[mi][nj], ah[mi], bl);
                    mma_bf16(acc[mi][nj], al[mi], bh);
                }
            }
        }
        __syncthreads();
    }

    // epilogue: c-fragment layout m16n8 -> direct gmem float2 stores
    const int l4 = lane >> 2;            // row 0..7
    const int l2 = (lane & 3) * 2;       // col 0,2,4,6
#pragma unroll
    for (int mi = 0; mi < 4; ++mi) {
#pragma unroll
        for (int nj = 0; nj < 4; ++nj) {
            const int colT = wn * 32 + nj * 8 + l2;       // 0..127 in tile
            const int o    = bn + colT;
            const float2 bia = *(const float2*)&bias[o];
#pragma unroll
            for (int half = 0; half < 2; ++half) {
                const int m = bm + wm * 64 + mi * 16 + l4 + half * 8;
                float2 v;
                v.x = acc[mi][nj][half * 2 + 0] + bia.x;
                v.y = acc[mi][nj][half * 2 + 1] + bia.y;
                if (MODE == 0) {
                    const int nh = blockIdx.x / 3;
                    const int t  = blockIdx.x % 3;
                    float* dst = (t == 0) ? g_q : (t == 1) ? g_k : g_v;
                    const int b = m / cS, s = m % cS;
                    *(float2*)&dst[((size_t)(b * cNH + nh) * cS + s) * cHD + colT] = v;
                } else {
                    const size_t idx = (size_t)m * cH + o;
                    const float2 res = *(const float2*)&residual[idx];
                    v.x += res.x; v.y += res.y;
                    *(float2*)&out[idx] = v;
                }
            }
        }
    }
}

// ---------------------------------------------------------------------------
// Kernel 2: causal flash attention with alibi (writes ctx as bf16 hi/lo)
// ---------------------------------------------------------------------------
__global__ __launch_bounds__(256) void attn_kernel(const float* __restrict__ alibi)
{
    extern __shared__ float smemf[];
    float* Qs = smemf;
    float* Ks = Qs + BQ * SD;
    float* Vs = Ks + BKT * SD;
    float* Ps = Vs + BKT * SD;
    float* mS = Ps + BQ * PD;
    float* lS = mS + BQ;

    const int qi  = blockIdx.x;
    const int bh  = blockIdx.y;
    const int b   = bh / cNH;
    const int nh  = bh % cNH;
    const int tid = threadIdx.x;
    const int ty  = tid >> 4;
    const int tx  = tid & 15;
    const size_t headbase = (size_t)bh * cS * cHD;
    const float inv_norm = 0.08838834764831845f;

    for (int i = tid; i < BQ * (cHD / 4); i += 256) {
        const int row = i / (cHD / 4);
        const int c4  = i % (cHD / 4);
        float4 v = *(const float4*)&g_q[headbase + (size_t)(qi * BQ + row) * cHD + c4 * 4];
        *(float4*)&Qs[row * SD + c4 * 4] = v;
    }
    if (tid < BQ) { mS[tid] = -INFINITY; lS[tid] = 0.f; }

    float o_acc[4][8];
#pragma unroll
    for (int i = 0; i < 4; i++)
#pragma unroll
        for (int j = 0; j < 8; j++) o_acc[i][j] = 0.f;

    __syncthreads();

    for (int kt = 0; kt <= qi; kt++) {
        for (int i = tid; i < BKT * (cHD / 4); i += 256) {
            const int row = i / (cHD / 4);
            const int c4  = i % (cHD / 4);
            const size_t src = headbase + (size_t)(kt * BKT + row) * cHD + c4 * 4;
            *(float4*)&Ks[row * SD + c4 * 4] = *(const float4*)&g_k[src];
            *(float4*)&Vs[row * SD + c4 * 4] = *(const float4*)&g_v[src];
        }
        __syncthreads();

        float s[4][4];
#pragma unroll
        for (int i = 0; i < 4; i++)
#pragma unroll
            for (int j = 0; j < 4; j++) s[i][j] = 0.f;

        for (int d = 0; d < cHD; d += 4) {
            float4 qv[4], kv[4];
#pragma unroll
            for (int i = 0; i < 4; i++)
                qv[i] = *(const float4*)&Qs[(ty * 4 + i) * SD + d];
#pragma unroll
            for (int j = 0; j < 4; j++)
                kv[j] = *(const float4*)&Ks[(tx + 16 * j) * SD + d];
#pragma unroll
            for (int i = 0; i < 4; i++)
#pragma unroll
                for (int j = 0; j < 4; j++) {
                    s[i][j] = fmaf(qv[i].x, kv[j].x, s[i][j]);
                    s[i][j] = fmaf(qv[i].y, kv[j].y, s[i][j]);
                    s[i][j] = fmaf(qv[i].z, kv[j].z, s[i][j]);
                    s[i][j] = fmaf(qv[i].w, kv[j].w, s[i][j]);
                }
        }

        int   kg[4];
        float al[4];
#pragma unroll
        for (int j = 0; j < 4; j++) {
            kg[j] = kt * BKT + tx + 16 * j;
            al[j] = alibi[(size_t)bh * cS + kg[j]];
        }
#pragma unroll
        for (int i = 0; i < 4; i++) {
            const int qg = qi * BQ + ty * 4 + i;
#pragma unroll
            for (int j = 0; j < 4; j++) {
                float sc = s[i][j] * inv_norm + al[j];
                s[i][j] = (kg[j] > qg) ? -100000.0f : sc;
            }
        }

        float mloc[4];
#pragma unroll
        for (int i = 0; i < 4; i++) {
            mloc[i] = fmaxf(fmaxf(s[i][0], s[i][1]), fmaxf(s[i][2], s[i][3]));
#pragma unroll
            for (int off = 8; off >= 1; off >>= 1)
                mloc[i] = fmaxf(mloc[i], __shfl_xor_sync(0xffffffffu, mloc[i], off, 16));
        }

        float m_new[4], scl[4], lloc[4];
#pragma unroll
        for (int i = 0; i < 4; i++) {
            const int r = ty * 4 + i;
            const float m_old = mS[r];
            m_new[i] = fmaxf(m_old, mloc[i]);
            scl[i]   = __expf(m_old - m_new[i]);
            lloc[i]  = 0.f;
#pragma unroll
            for (int j = 0; j < 4; j++) {
                const float p = __expf(s[i][j] - m_new[i]);
                Ps[r * PD + tx + 16 * j] = p;
                lloc[i] += p;
            }
#pragma unroll
            for (int off = 8; off >= 1; off >>= 1)
                lloc[i] += __shfl_xor_sync(0xffffffffu, lloc[i], off, 16);
        }
        if (tx == 0) {
#pragma unroll
            for (int i = 0; i < 4; i++) {
                const int r = ty * 4 + i;
                mS[r] = m_new[i];
                lS[r] = lS[r] * scl[i] + lloc[i];
            }
        }
        __syncthreads();

#pragma unroll
        for (int i = 0; i < 4; i++)
#pragma unroll
            for (int j = 0; j < 8; j++) o_acc[i][j] *= scl[i];

        for (int kk = 0; kk < BKT; kk++) {
            float p[4];
#pragma unroll
            for (int i = 0; i < 4; i++) p[i] = Ps[(ty * 4 + i) * PD + kk];
            const float4 v0 = *(const float4*)&Vs[kk * SD + tx * 8];
            const float4 v1 = *(const float4*)&Vs[kk * SD + tx * 8 + 4];
#pragma unroll
            for (int i = 0; i < 4; i++) {
                o_acc[i][0] = fmaf(p[i], v0.x, o_acc[i][0]);
                o_acc[i][1] = fmaf(p[i], v0.y, o_acc[i][1]);
                o_acc[i][2] = fmaf(p[i], v0.z, o_acc[i][2]);
                o_acc[i][3] = fmaf(p[i], v0.w, o_acc[i][3]);
                o_acc[i][4] = fmaf(p[i], v1.x, o_acc[i][4]);
                o_acc[i][5] = fmaf(p[i], v1.y, o_acc[i][5]);
                o_acc[i][6] = fmaf(p[i], v1.z, o_acc[i][6]);
                o_acc[i][7] = fmaf(p[i], v1.w, o_acc[i][7]);
            }
        }
        __syncthreads();
    }

#pragma unroll
    for (int i = 0; i < 4; i++) {
        const int r = ty * 4 + i;
        const float inv_l = 1.0f / lS[r];
        const int qg = qi * BQ + r;
        const size_t base = (size_t)(b * cS + qg) * cH + nh * cHD + tx * 8;
#pragma unroll
        for (int j = 0; j < 8; j++) {
            const float v = o_acc[i][j] * inv_l;
            const __nv_bfloat16 h = __float2bfloat16_rn(v);
            g_ctx_hi[base + j] = h;
            g_ctx_lo[base + j] = __float2bfloat16_rn(v - __bfloat162float(h));
        }
    }
}

// ---------------------------------------------------------------------------
// Launch
// ---------------------------------------------------------------------------
extern "C" void kernel_launch(void* const* d_in, const int* in_sizes, int n_in,
                              void* d_out, int out_size)
{
    (void)in_sizes; (void)n_in; (void)out_size;
    const float* hidden   = (const float*)d_in[0];
    const float* residual = (const float*)d_in[1];
    const float* alibi    = (const float*)d_in[2];
    const float* W_qkv    = (const float*)d_in[4];
    const float* b_qkv    = (const float*)d_in[5];
    const float* W_dense  = (const float*)d_in[6];
    const float* b_dense  = (const float*)d_in[7];
    float* out = (float*)d_out;

    const int attn_smem = (3 * BQ * SD + BQ * PD + 2 * BQ) * (int)sizeof(float);
    cudaFuncSetAttribute(tc_gemm<0>, cudaFuncAttributeMaxDynamicSharedMemorySize, GEMM_SMEM);
    cudaFuncSetAttribute(tc_gemm<1>, cudaFuncAttributeMaxDynamicSharedMemorySize, GEMM_SMEM);
    cudaFuncSetAttribute(attn_kernel, cudaFuncAttributeMaxDynamicSharedMemorySize, attn_smem);

    __nv_bfloat16 *hid_hi, *hid_lo, *wq_hi, *wq_lo, *wd_hi, *wd_lo, *cx_hi, *cx_lo;
    cudaGetSymbolAddress((void**)&hid_hi, g_hid_hi);
    cudaGetSymbolAddress((void**)&hid_lo, g_hid_lo);
    cudaGetSymbolAddress((void**)&wq_hi,  g_wqkv_hi);
    cudaGetSymbolAddress((void**)&wq_lo,  g_wqkv_lo);
    cudaGetSymbolAddress((void**)&wd_hi,  g_wd_hi);
    cudaGetSymbolAddress((void**)&wd_lo,  g_wd_lo);
    cudaGetSymbolAddress((void**)&cx_hi,  g_ctx_hi);
    cudaGetSymbolAddress((void**)&cx_lo,  g_ctx_lo);

    // 0) fp32 -> bf16 hi/lo splits
    split_fp32<<<(cM * cH) / 1024, 256>>>((const float4*)hidden,
        (__nv_bfloat162*)hid_hi, (__nv_bfloat162*)hid_lo);
    split_fp32<<<(cQKVN * cH) / 1024, 256>>>((const float4*)W_qkv,
        (__nv_bfloat162*)wq_hi, (__nv_bfloat162*)wq_lo);
    split_fp32<<<(cH * cH) / 1024, 256>>>((const float4*)W_dense,
        (__nv_bfloat162*)wd_hi, (__nv_bfloat162*)wd_lo);

    // 1) QKV GEMM (mma.sync) -> g_q/g_k/g_v
    tc_gemm<0><<<dim3(cQKVN / GBN, cM / GBM), 256, GEMM_SMEM>>>(
        hid_hi, hid_lo, wq_hi, wq_lo, b_qkv, nullptr, nullptr);

    // 2) attention -> g_ctx_hi/lo
    attn_kernel<<<dim3(cS / BQ, cB * cNH), 256, attn_smem>>>(alibi);

    // 3) dense GEMM (mma.sync) + bias + residual -> out
    tc_gemm<1><<<dim3(cH / GBN, cM / GBM), 256, GEMM_SMEM>>>(
        cx_hi, cx_lo, wd_hi, wd_lo, b_dense, residual, out);
}

// round 5
// speedup vs baseline: 3.0939x; 1.3652x over previous
#include <cuda_runtime.h>
#include <cuda_bf16.h>
#include <math.h>
#include <cstdint>

// ---------------------------------------------------------------------------
// Problem constants
// ---------------------------------------------------------------------------
namespace {
constexpr int cB  = 2;
constexpr int cS  = 2048;
constexpr int cH  = 4096;
constexpr int cNH = 32;
constexpr int cHD = 128;
constexpr int cM  = cB * cS;      // 4096
constexpr int cQKVN = 3 * cH;     // 12288

// GEMM tiling (mma.sync path)
constexpr int GBM = 128, GBN = 128, GBK = 32;
constexpr int SKB   = 80;                 // smem row stride bytes
constexpr int TILEB = GBM * SKB;
constexpr int STAGEB = 4 * TILEB;
constexpr int GEMM_SMEM = 2 * STAGEB;     // 81920

// Attention tiling (mma.sync)
constexpr int ABQ = 64, ABK = 64;
constexpr int AST = 136;                  // bf16 elems per smem row (272 B)
constexpr int AKTILE = ABK * AST * 2;     // 17408 B per tile
constexpr int AOFF_KH = 0;
constexpr int AOFF_KL = AKTILE;
constexpr int AOFF_VH = 2 * AKTILE;
constexpr int AOFF_VL = 3 * AKTILE;
constexpr int AOFF_ALI = 4 * AKTILE;      // 64 floats
constexpr int ATTN_SMEM = AOFF_ALI + 256; // 69888
}

// ---------------------------------------------------------------------------
// Scratch (__device__ globals)
// ---------------------------------------------------------------------------
__device__ __nv_bfloat16 g_qh[(size_t)cB * cNH * cS * cHD];
__device__ __nv_bfloat16 g_ql[(size_t)cB * cNH * cS * cHD];
__device__ __nv_bfloat16 g_kh[(size_t)cB * cNH * cS * cHD];
__device__ __nv_bfloat16 g_kl[(size_t)cB * cNH * cS * cHD];
__device__ __nv_bfloat16 g_vh[(size_t)cB * cNH * cS * cHD];
__device__ __nv_bfloat16 g_vl[(size_t)cB * cNH * cS * cHD];

__device__ __nv_bfloat16 g_hid_hi[(size_t)cM * cH];
__device__ __nv_bfloat16 g_hid_lo[(size_t)cM * cH];
__device__ __nv_bfloat16 g_wqkv_hi[(size_t)cQKVN * cH];
__device__ __nv_bfloat16 g_wqkv_lo[(size_t)cQKVN * cH];
__device__ __nv_bfloat16 g_wd_hi[(size_t)cH * cH];
__device__ __nv_bfloat16 g_wd_lo[(size_t)cH * cH];
__device__ __nv_bfloat16 g_ctx_hi[(size_t)cM * cH];
__device__ __nv_bfloat16 g_ctx_lo[(size_t)cM * cH];

// ---------------------------------------------------------------------------
// PTX helpers — non-arch-specific only (mma.sync / ldmatrix / cp.async)
// ---------------------------------------------------------------------------
__device__ __forceinline__ uint32_t smem_u32(const void* p) {
    uint32_t a;
    asm("{ .reg .u64 t; cvta.to.shared.u64 t, %1; cvt.u32.u64 %0, t; }" : "=r"(a) : "l"(p));
    return a;
}
__device__ __forceinline__ void mma_bf16(float* c, const uint32_t* a, const uint32_t* b) {
    asm volatile(
        "mma.sync.aligned.m16n8k16.row.col.f32.bf16.bf16.f32 "
        "{%0,%1,%2,%3}, {%4,%5,%6,%7}, {%8,%9}, {%0,%1,%2,%3};"
        : "+f"(c[0]), "+f"(c[1]), "+f"(c[2]), "+f"(c[3])
        : "r"(a[0]), "r"(a[1]), "r"(a[2]), "r"(a[3]), "r"(b[0]), "r"(b[1]));
}
__device__ __forceinline__ void ldsm_x4(uint32_t* r, uint32_t addr) {
    asm volatile("ldmatrix.sync.aligned.m8n8.x4.shared.b16 {%0,%1,%2,%3}, [%4];"
                 : "=r"(r[0]), "=r"(r[1]), "=r"(r[2]), "=r"(r[3]) : "r"(addr));
}
__device__ __forceinline__ void ldsm_x4_t(uint32_t* r, uint32_t addr) {
    asm volatile("ldmatrix.sync.aligned.m8n8.x4.trans.shared.b16 {%0,%1,%2,%3}, [%4];"
                 : "=r"(r[0]), "=r"(r[1]), "=r"(r[2]), "=r"(r[3]) : "r"(addr));
}
__device__ __forceinline__ void ldsm_x2(uint32_t* r, uint32_t addr) {
    asm volatile("ldmatrix.sync.aligned.m8n8.x2.shared.b16 {%0,%1}, [%2];"
                 : "=r"(r[0]), "=r"(r[1]) : "r"(addr));
}
__device__ __forceinline__ void cp_async16(uint32_t s, const void* g) {
    asm volatile("cp.async.cg.shared.global [%0], [%1], 16;" :: "r"(s), "l"(g));
}
#define CP_COMMIT() asm volatile("cp.async.commit_group;" ::: "memory")
#define CP_WAIT(n)  asm volatile("cp.async.wait_group %0;" :: "n"(n) : "memory")

__device__ __forceinline__ uint32_t pack_bf16(float lo, float hi) {
    uint32_t r;
    asm("cvt.rn.bf16x2.f32 %0, %1, %2;" : "=r"(r) : "f"(hi), "f"(lo));
    return r;
}
__device__ __forceinline__ float bf16_round(float x) {
    return __bfloat162float(__float2bfloat16_rn(x));
}
// exp on the FMA pipe: valid for x <= 0; flushes to ~0 below -87 (matches fp32
// reference where exp(-1e5 - m) underflows to exactly 0 in the l-sum scale).
__device__ __forceinline__ float fast_exp(float x) {
    x = fmaxf(x, -87.0f);
    const float L2E = 1.4426950408889634f;
    float t = fmaf(x, L2E, 12582912.0f);
    float i = t - 12582912.0f;
    float f = fmaf(x, L2E, -i);
    float p =        1.3394582e-3f;
    p = fmaf(p, f, 9.6180217e-3f);
    p = fmaf(p, f, 5.5503368e-2f);
    p = fmaf(p, f, 2.4022652e-1f);
    p = fmaf(p, f, 6.9314718e-1f);
    p = fmaf(p, f, 1.0f);
    int e = (int)i;
    return __int_as_float((uint32_t)(e + 127) << 23) * p;
}

// ---------------------------------------------------------------------------
// fp32 -> (bf16 hi, bf16 lo) split
// ---------------------------------------------------------------------------
__global__ __launch_bounds__(256) void split_fp32(
    const float4* __restrict__ src,
    __nv_bfloat162* __restrict__ hi,
    __nv_bfloat162* __restrict__ lo)
{
    const size_t i = (size_t)blockIdx.x * 256 + threadIdx.x;
    const float4 v = src[i];
    __nv_bfloat16 hx = __float2bfloat16_rn(v.x);
    __nv_bfloat16 hy = __float2bfloat16_rn(v.y);
    __nv_bfloat16 hz = __float2bfloat16_rn(v.z);
    __nv_bfloat16 hw = __float2bfloat16_rn(v.w);
    hi[2 * i]     = __nv_bfloat162(hx, hy);
    hi[2 * i + 1] = __nv_bfloat162(hz, hw);
    lo[2 * i]     = __nv_bfloat162(__float2bfloat16_rn(v.x - __bfloat162float(hx)),
                                   __float2bfloat16_rn(v.y - __bfloat162float(hy)));
    lo[2 * i + 1] = __nv_bfloat162(__float2bfloat16_rn(v.z - __bfloat162float(hz)),
                                   __float2bfloat16_rn(v.w - __bfloat162float(hw)));
}

// ---------------------------------------------------------------------------
// Tensor GEMM via mma.sync: C = A * B^T (3-term bf16 split)
// MODE 0: QKV -> scatter bf16 hi/lo into g_q*/g_k*/g_v* (+bias)
// MODE 1: dense -> out = acc + bias + residual (fp32)
// ---------------------------------------------------------------------------
template <int MODE>
__global__ __launch_bounds__(256, 2) void tc_gemm(
    const __nv_bfloat16* __restrict__ Ahi, const __nv_bfloat16* __restrict__ Alo,
    const __nv_bfloat16* __restrict__ Bhi, const __nv_bfloat16* __restrict__ Blo,
    const float* __restrict__ bias,
    const float* __restrict__ residual,
    float* __restrict__ out)
{
    extern __shared__ char smem[];
    const uint32_t sbase = smem_u32(smem);
    const int tid  = threadIdx.x;
    const int wid  = tid >> 5;
    const int lane = tid & 31;
    const int wm   = wid >> 2;
    const int wn   = wid & 3;
    const int bm   = blockIdx.y * GBM;
    const int bn   = blockIdx.x * GBN;

    const __nv_bfloat16* Ah = Ahi + (size_t)bm * cH;
    const __nv_bfloat16* Al = Alo + (size_t)bm * cH;
    const __nv_bfloat16* Bh = Bhi + (size_t)bn * cH;
    const __nv_bfloat16* Bl = Blo + (size_t)bn * cH;

    float acc[4][4][4];
#pragma unroll
    for (int mi = 0; mi < 4; mi++)
#pragma unroll
        for (int nj = 0; nj < 4; nj++)
#pragma unroll
            for (int r = 0; r < 4; r++) acc[mi][nj][r] = 0.f;

    const int aRow = ((lane >> 3) & 1) * 8 + (lane & 7);
    const int aK   = (lane >> 4) * 8;
    const int bl15 = lane & 15;
    const int bN   = bl15 & 7;
    const int bK   = (bl15 >> 3) * 8;

    auto load_chunk = [&](uint32_t stage, int k0) {
#pragma unroll
        for (int it = 0; it < 2; ++it) {
            const int c   = tid + it * 256;
            const int row = c >> 2;
            const int kc  = c & 3;
            const uint32_t so = (uint32_t)(row * SKB + kc * 16);
            const size_t  go  = (size_t)row * cH + k0 + kc * 8;
            cp_async16(stage + 0 * TILEB + so, Ah + go);
            cp_async16(stage + 1 * TILEB + so, Al + go);
            cp_async16(stage + 2 * TILEB + so, Bh + go);
            cp_async16(stage + 3 * TILEB + so, Bl + go);
        }
    };

    constexpr int NCH = cH / GBK;
    load_chunk(sbase, 0);
    CP_COMMIT();

    for (int ch = 0; ch < NCH; ++ch) {
        if (ch + 1 < NCH) {
            load_chunk(sbase + ((ch + 1) & 1) * STAGEB, (ch + 1) * GBK);
            CP_COMMIT();
            CP_WAIT(1);
        } else {
            CP_WAIT(0);
        }
        __syncthreads();

        const uint32_t st = sbase + (ch & 1) * STAGEB;
#pragma unroll
        for (int ks = 0; ks < 2; ++ks) {
            uint32_t ah[4][4], al[4][4];
#pragma unroll
            for (int mi = 0; mi < 4; ++mi) {
                const uint32_t ao =
                    (uint32_t)((wm * 64 + mi * 16 + aRow) * SKB + (ks * 16 + aK) * 2);
                ldsm_x4(ah[mi], st + 0 * TILEB + ao);
                ldsm_x4(al[mi], st + 1 * TILEB + ao);
            }
#pragma unroll
            for (int nj = 0; nj < 4; ++nj) {
                const uint32_t bo =
                    (uint32_t)((wn * 32 + nj * 8 + bN) * SKB + (ks * 16 + bK) * 2);
                uint32_t bh[2], bl[2];
                ldsm_x2(bh, st + 2 * TILEB + bo);
                ldsm_x2(bl, st + 3 * TILEB + bo);
#pragma unroll
                for (int mi = 0; mi < 4; ++mi) {
                    mma_bf16(acc[mi][nj], ah[mi], bh);
                    mma_bf16(acc[mi][nj], ah[mi], bl);
                    mma_bf16(acc[mi][nj], al[mi], bh);
                }
            }
        }
        __syncthreads();
    }

    const int l4 = lane >> 2;
    const int l2 = (lane & 3) * 2;
#pragma unroll
    for (int mi = 0; mi < 4; ++mi) {
#pragma unroll
        for (int nj = 0; nj < 4; ++nj) {
            const int colT = wn * 32 + nj * 8 + l2;
            const int o    = bn + colT;
            const float2 bia = *(const float2*)&bias[o];
#pragma unroll
            for (int half = 0; half < 2; ++half) {
                const int m = bm + wm * 64 + mi * 16 + l4 + half * 8;
                float vx = acc[mi][nj][half * 2 + 0] + bia.x;
                float vy = acc[mi][nj][half * 2 + 1] + bia.y;
                if (MODE == 0) {
                    const int nh = blockIdx.x / 3;
                    const int t  = blockIdx.x % 3;
                    __nv_bfloat16* dh = (t == 0) ? g_qh : (t == 1) ? g_kh : g_vh;
                    __nv_bfloat16* dl = (t == 0) ? g_ql : (t == 1) ? g_kl : g_vl;
                    const int b = m / cS, s = m % cS;
                    const size_t idx = ((size_t)(b * cNH + nh) * cS + s) * cHD + colT;
                    const float rx = bf16_round(vx), ry = bf16_round(vy);
                    *(uint32_t*)&dh[idx] = pack_bf16(vx, vy);
                    *(uint32_t*)&dl[idx] = pack_bf16(vx - rx, vy - ry);
                } else {
                    const size_t idx = (size_t)m * cH + o;
                    const float2 res = *(const float2*)&residual[idx];
                    float2 v; v.x = vx + res.x; v.y = vy + res.y;
                    *(float2*)&out[idx] = v;
                }
            }
        }
    }
}

// ---------------------------------------------------------------------------
// Attention via mma.sync: 64 q-rows/CTA, 4 warps (16 rows each), K-tiles of 64.
// 3-term bf16 split for QK and PV; register-resident online softmax.
// ---------------------------------------------------------------------------
__global__ __launch_bounds__(128) void attn_mma(const float* __restrict__ alibi)
{
    extern __shared__ char sm[];
    const uint32_t sb = smem_u32(sm);
    const int tid  = threadIdx.x;
    const int lane = tid & 31;
    const int w    = tid >> 5;
    const int qi   = (cS / ABQ - 1) - blockIdx.x;   // big tiles first
    const int bh   = blockIdx.y;
    const int b    = bh >> 5;
    const int nh   = bh & 31;
    const size_t hb = (size_t)bh * cS * cHD;
    const float inv_norm = 0.08838834764831845f;

    const int g    = lane >> 2;
    const int tig  = lane & 3;
    const int aRow = ((lane >> 3) & 1) * 8 + (lane & 7);
    const int aK   = (lane >> 4) * 8;
    const int bRow = (lane & 7) + ((lane >> 4) << 3);       // QK B x4: n in 16
    const int bKc  = ((lane >> 3) & 1) * 8;
    const int vRow = (lane & 7) + (((lane >> 3) & 1) << 3); // V trans x4: kv in 16
    const int vSel = lane >> 4;                             // 0/1 -> d tile pair

    // ---- stage Q into smem (reuse K area), ldmatrix into registers
#pragma unroll
    for (int i = 0; i < 8; i++) {
        const int id = tid + i * 128;
        const int r = id >> 4, c = id & 15;
        const size_t go = hb + (size_t)(qi * ABQ + r) * cHD + c * 8;
        const uint32_t so = (uint32_t)(r * (AST * 2) + c * 16);
        cp_async16(sb + AOFF_KH + so, g_qh + go);
        cp_async16(sb + AOFF_KL + so, g_ql + go);
    }
    CP_COMMIT(); CP_WAIT(0);
    __syncthreads();

    uint32_t qh[8][4], ql[8][4];
#pragma unroll
    for (int ks = 0; ks < 8; ks++) {
        const uint32_t ao = (uint32_t)((w * 16 + aRow) * (AST * 2) + (ks * 16 + aK) * 2);
        ldsm_x4(qh[ks], sb + AOFF_KH + ao);
        ldsm_x4(ql[ks], sb + AOFF_KL + ao);
    }
    __syncthreads();

    float ctx[16][4];
#pragma unroll
    for (int t = 0; t < 16; t++)
#pragma unroll
        for (int r = 0; r < 4; r++) ctx[t][r] = 0.f;
    float m1 = -INFINITY, m2 = -INFINITY, l1 = 0.f, l2 = 0.f;
    const int row1 = qi * ABQ + w * 16 + g;
    const int row2 = row1 + 8;

    for (int kt = 0; kt <= qi; kt++) {
        // load K/V hi/lo tiles + alibi
#pragma unroll
        for (int i = 0; i < 8; i++) {
            const int id = tid + i * 128;
            const int r = id >> 4, c = id & 15;
            const size_t go = hb + (size_t)(kt * ABK + r) * cHD + c * 8;
            const uint32_t so = (uint32_t)(r * (AST * 2) + c * 16);
            cp_async16(sb + AOFF_KH + so, g_kh + go);
            cp_async16(sb + AOFF_KL + so, g_kl + go);
            cp_async16(sb + AOFF_VH + so, g_vh + go);
            cp_async16(sb + AOFF_VL + so, g_vl + go);
        }
        if (tid < 64)
            ((float*)(sm + AOFF_ALI))[tid] = alibi[(size_t)bh * cS + kt * ABK + tid];
        CP_COMMIT(); CP_WAIT(0);
        __syncthreads();

        // ---- S = Q K^T
        float sacc[8][4];
#pragma unroll
        for (int t = 0; t < 8; t++)
#pragma unroll
            for (int r = 0; r < 4; r++) sacc[t][r] = 0.f;

#pragma unroll
        for (int p = 0; p < 4; p++) {
#pragma unroll
            for (int ks = 0; ks < 8; ks++) {
                uint32_t kbh[4], kbl[4];
                const uint32_t bo =
                    (uint32_t)((p * 16 + bRow) * (AST * 2) + (ks * 16 + bKc) * 2);
                ldsm_x4(kbh, sb + AOFF_KH + bo);
                ldsm_x4(kbl, sb + AOFF_KL + bo);
                mma_bf16(sacc[2 * p],     qh[ks], kbh);
                mma_bf16(sacc[2 * p],     qh[ks], kbl);
                mma_bf16(sacc[2 * p],     ql[ks], kbh);
                mma_bf16(sacc[2 * p + 1], qh[ks], kbh + 2);
                mma_bf16(sacc[2 * p + 1], qh[ks], kbl + 2);
                mma_bf16(sacc[2 * p + 1], ql[ks], kbh + 2);
            }
        }

        // ---- scale + alibi + causal mask (diag tile only)
        const bool diag = (kt == qi);
        const float* als = (const float*)(sm + AOFF_ALI);
#pragma unroll
        for (int t = 0; t < 8; t++) {
            const int c0 = t * 8 + tig * 2;
            const float a0 = als[c0], a1 = als[c0 + 1];
            sacc[t][0] = fmaf(sacc[t][0], inv_norm, a0);
            sacc[t][1] = fmaf(sacc[t][1], inv_norm, a1);
            sacc[t][2] = fmaf(sacc[t][2], inv_norm, a0);
            sacc[t][3] = fmaf(sacc[t][3], inv_norm, a1);
            if (diag) {
                const int cg = kt * ABK + c0;
                if (cg     > row1) sacc[t][0] = -100000.0f;
                if (cg + 1 > row1) sacc[t][1] = -100000.0f;
                if (cg     > row2) sacc[t][2] = -100000.0f;
                if (cg + 1 > row2) sacc[t][3] = -100000.0f;
            }
        }

        // ---- online softmax (register-resident; 4-lane row groups)
        float mx1 = -INFINITY, mx2 = -INFINITY;
#pragma unroll
        for (int t = 0; t < 8; t++) {
            mx1 = fmaxf(mx1, fmaxf(sacc[t][0], sacc[t][1]));
            mx2 = fmaxf(mx2, fmaxf(sacc[t][2], sacc[t][3]));
        }
        mx1 = fmaxf(mx1, __shfl_xor_sync(0xffffffffu, mx1, 1));
        mx1 = fmaxf(mx1, __shfl_xor_sync(0xffffffffu, mx1, 2));
        mx2 = fmaxf(mx2, __shfl_xor_sync(0xffffffffu, mx2, 1));
        mx2 = fmaxf(mx2, __shfl_xor_sync(0xffffffffu, mx2, 2));

        const float mn1 = fmaxf(m1, mx1), mn2 = fmaxf(m2, mx2);
        const float sc1 = fast_exp(m1 - mn1), sc2 = fast_exp(m2 - mn2);
        float ls1 = 0.f, ls2 = 0.f;
#pragma unroll
        for (int t = 0; t < 8; t++) {
            sacc[t][0] = fast_exp(sacc[t][0] - mn1);
            sacc[t][1] = fast_exp(sacc[t][1] - mn1);
            sacc[t][2] = fast_exp(sacc[t][2] - mn2);
            sacc[t][3] = fast_exp(sacc[t][3] - mn2);
            ls1 += sacc[t][0] + sacc[t][1];
            ls2 += sacc[t][2] + sacc[t][3];
        }
        ls1 += __shfl_xor_sync(0xffffffffu, ls1, 1);
        ls1 += __shfl_xor_sync(0xffffffffu, ls1, 2);
        ls2 += __shfl_xor_sync(0xffffffffu, ls2, 1);
        ls2 += __shfl_xor_sync(0xffffffffu, ls2, 2);
        l1 = l1 * sc1 + ls1;  l2 = l2 * sc2 + ls2;
        m1 = mn1;             m2 = mn2;
#pragma unroll
        for (int t = 0; t < 16; t++) {
            ctx[t][0] *= sc1; ctx[t][1] *= sc1;
            ctx[t][2] *= sc2; ctx[t][3] *= sc2;
        }

        // ---- ctx += P V  (P repacked in-register to A fragments, hi/lo)
#pragma unroll
        for (int ks = 0; ks < 4; ks++) {
            const float p00 = sacc[2 * ks][0],     p01 = sacc[2 * ks][1];
            const float p02 = sacc[2 * ks][2],     p03 = sacc[2 * ks][3];
            const float p10 = sacc[2 * ks + 1][0], p11 = sacc[2 * ks + 1][1];
            const float p12 = sacc[2 * ks + 1][2], p13 = sacc[2 * ks + 1][3];
            uint32_t pah[4], pal[4];
            pah[0] = pack_bf16(p00, p01);
            pah[1] = pack_bf16(p02, p03);
            pah[2] = pack_bf16(p10, p11);
            pah[3] = pack_bf16(p12, p13);
            pal[0] = pack_bf16(p00 - bf16_round(p00), p01 - bf16_round(p01));
            pal[1] = pack_bf16(p02 - bf16_round(p02), p03 - bf16_round(p03));
            pal[2] = pack_bf16(p10 - bf16_round(p10), p11 - bf16_round(p11));
            pal[3] = pack_bf16(p12 - bf16_round(p12), p13 - bf16_round(p13));
#pragma unroll
            for (int p2 = 0; p2 < 8; p2++) {
                uint32_t vbh[4], vbl[4];
                const uint32_t vo =
                    (uint32_t)((ks * 16 + vRow) * (AST * 2) + (p2 * 16 + vSel * 8) * 2);
                ldsm_x4_t(vbh, sb + AOFF_VH + vo);
                ldsm_x4_t(vbl, sb + AOFF_VL + vo);
                mma_bf16(ctx[2 * p2],     pah, vbh);
                mma_bf16(ctx[2 * p2],     pah, vbl);
                mma_bf16(ctx[2 * p2],     pal, vbh);
                mma_bf16(ctx[2 * p2 + 1], pah, vbh + 2);
                mma_bf16(ctx[2 * p2 + 1], pah, vbl + 2);
                mma_bf16(ctx[2 * p2 + 1], pal, vbh + 2);
            }
        }
        __syncthreads();
    }

    // ---- epilogue: normalize, split to bf16 hi/lo ctx
    const float inv1 = 1.0f / l1, inv2 = 1.0f / l2;
    const size_t o1 = (size_t)(b * cS + row1) * cH + nh * cHD;
    const size_t o2 = (size_t)(b * cS + row2) * cH + nh * cHD;
#pragma unroll
    for (int t = 0; t < 16; t++) {
        const int d = t * 8 + tig * 2;
        const float v0 = ctx[t][0] * inv1, v1 = ctx[t][1] * inv1;
        const float v2 = ctx[t][2] * inv2, v3 = ctx[t][3] * inv2;
        *(uint32_t*)&g_ctx_hi[o1 + d] = pack_bf16(v0, v1);
        *(uint32_t*)&g_ctx_lo[o1 + d] = pack_bf16(v0 - bf16_round(v0), v1 - bf16_round(v1));
        *(uint32_t*)&g_ctx_hi[o2 + d] = pack_bf16(v2, v3);
        *(uint32_t*)&g_ctx_lo[o2 + d] = pack_bf16(v2 - bf16_round(v2), v3 - bf16_round(v3));
    }
}

// ---------------------------------------------------------------------------
// Launch
// ---------------------------------------------------------------------------
extern "C" void kernel_launch(void* const* d_in, const int* in_sizes, int n_in,
                              void* d_out, int out_size)
{
    (void)in_sizes; (void)n_in; (void)out_size;
    const float* hidden   = (const float*)d_in[0];
    const float* residual = (const float*)d_in[1];
    const float* alibi    = (const float*)d_in[2];
    const float* W_qkv    = (const float*)d_in[4];
    const float* b_qkv    = (const float*)d_in[5];
    const float* W_dense  = (const float*)d_in[6];
    const float* b_dense  = (const float*)d_in[7];
    float* out = (float*)d_out;

    cudaFuncSetAttribute(tc_gemm<0>, cudaFuncAttributeMaxDynamicSharedMemorySize, GEMM_SMEM);
    cudaFuncSetAttribute(tc_gemm<1>, cudaFuncAttributeMaxDynamicSharedMemorySize, GEMM_SMEM);
    cudaFuncSetAttribute(attn_mma,  cudaFuncAttributeMaxDynamicSharedMemorySize, ATTN_SMEM);

    __nv_bfloat16 *hid_hi, *hid_lo, *wq_hi, *wq_lo, *wd_hi, *wd_lo, *cx_hi, *cx_lo;
    cudaGetSymbolAddress((void**)&hid_hi, g_hid_hi);
    cudaGetSymbolAddress((void**)&hid_lo, g_hid_lo);
    cudaGetSymbolAddress((void**)&wq_hi,  g_wqkv_hi);
    cudaGetSymbolAddress((void**)&wq_lo,  g_wqkv_lo);
    cudaGetSymbolAddress((void**)&wd_hi,  g_wd_hi);
    cudaGetSymbolAddress((void**)&wd_lo,  g_wd_lo);
    cudaGetSymbolAddress((void**)&cx_hi,  g_ctx_hi);
    cudaGetSymbolAddress((void**)&cx_lo,  g_ctx_lo);

    // 0) fp32 -> bf16 hi/lo splits
    split_fp32<<<(cM * cH) / 1024, 256>>>((const float4*)hidden,
        (__nv_bfloat162*)hid_hi, (__nv_bfloat162*)hid_lo);
    split_fp32<<<(cQKVN * cH) / 1024, 256>>>((const float4*)W_qkv,
        (__nv_bfloat162*)wq_hi, (__nv_bfloat162*)wq_lo);
    split_fp32<<<(cH * cH) / 1024, 256>>>((const float4*)W_dense,
        (__nv_bfloat162*)wd_hi, (__nv_bfloat162*)wd_lo);

    // 1) QKV GEMM -> q/k/v bf16 hi/lo
    tc_gemm<0><<<dim3(cQKVN / GBN, cM / GBM), 256, GEMM_SMEM>>>(
        hid_hi, hid_lo, wq_hi, wq_lo, b_qkv, nullptr, nullptr);

    // 2) attention (tensor) -> ctx bf16 hi/lo
    attn_mma<<<dim3(cS / ABQ, cB * cNH), 128, ATTN_SMEM>>>(alibi);

    // 3) dense GEMM + bias + residual -> out
    tc_gemm<1><<<dim3(cH / GBN, cM / GBM), 256, GEMM_SMEM>>>(
        cx_hi, cx_lo, wd_hi, wd_lo, b_dense, residual, out);
}

// round 8
// speedup vs baseline: 3.1329x; 1.0126x over previous
#include <cuda_runtime.h>
#include <cuda_bf16.h>
#include <math.h>
#include <cstdint>

// ---------------------------------------------------------------------------
// Problem constants
// ---------------------------------------------------------------------------
namespace {
constexpr int cB  = 2;
constexpr int cS  = 2048;
constexpr int cH  = 4096;
constexpr int cNH = 32;
constexpr int cHD = 128;
constexpr int cM  = cB * cS;      // 4096
constexpr int cQKVN = 3 * cH;     // 12288

// GEMM tiling (mma.sync path)
constexpr int GBM = 128, GBN = 128, GBK = 32;
constexpr int SKB   = 80;                 // smem row stride bytes (conflict-free for ldsm)
constexpr int TILEB = GBM * SKB;
constexpr int STAGEB = 4 * TILEB;
constexpr int GEMM_SMEM = 2 * STAGEB;     // 81920

// Attention tiling: q-tile 64 rows, k-tile 32 rows, double-buffered
constexpr int ABQ = 64;
constexpr int ROWB = 272;                 // 128 bf16 + 8 pad = 272 bytes
constexpr int ATILE = 32 * ROWB;          // 8704 per tile (32 rows)
constexpr int ASTAGE = 4 * ATILE;         // KH,KL,VH,VL = 34816
constexpr int AOFF_ALI = 2 * ASTAGE;      // 69632
constexpr int ATTN_SMEM = AOFF_ALI + 256; // 69888 (3 CTAs/SM)
}

// ---------------------------------------------------------------------------
// Scratch (__device__ globals)
// ---------------------------------------------------------------------------
__device__ __nv_bfloat16 g_qh[(size_t)cB * cNH * cS * cHD];
__device__ __nv_bfloat16 g_ql[(size_t)cB * cNH * cS * cHD];
__device__ __nv_bfloat16 g_kh[(size_t)cB * cNH * cS * cHD];
__device__ __nv_bfloat16 g_kl[(size_t)cB * cNH * cS * cHD];
__device__ __nv_bfloat16 g_vh[(size_t)cB * cNH * cS * cHD];
__device__ __nv_bfloat16 g_vl[(size_t)cB * cNH * cS * cHD];

__device__ __nv_bfloat16 g_hid_hi[(size_t)cM * cH];
__device__ __nv_bfloat16 g_hid_lo[(size_t)cM * cH];
__device__ __nv_bfloat16 g_wqkv_hi[(size_t)cQKVN * cH];
__device__ __nv_bfloat16 g_wqkv_lo[(size_t)cQKVN * cH];
__device__ __nv_bfloat16 g_wd_hi[(size_t)cH * cH];
__device__ __nv_bfloat16 g_wd_lo[(size_t)cH * cH];
__device__ __nv_bfloat16 g_ctx_hi[(size_t)cM * cH];
__device__ __nv_bfloat16 g_ctx_lo[(size_t)cM * cH];

// ---------------------------------------------------------------------------
// PTX helpers — non-arch-specific only (mma.sync / ldmatrix / cp.async)
// ---------------------------------------------------------------------------
__device__ __forceinline__ uint32_t smem_u32(const void* p) {
    uint32_t a;
    asm("{ .reg .u64 t; cvta.to.shared.u64 t, %1; cvt.u32.u64 %0, t; }" : "=r"(a) : "l"(p));
    return a;
}
__device__ __forceinline__ void mma_bf16(float* c, const uint32_t* a, const uint32_t* b) {
    asm volatile(
        "mma.sync.aligned.m16n8k16.row.col.f32.bf16.bf16.f32 "
        "{%0,%1,%2,%3}, {%4,%5,%6,%7}, {%8,%9}, {%0,%1,%2,%3};"
        : "+f"(c[0]), "+f"(c[1]), "+f"(c[2]), "+f"(c[3])
        : "r"(a[0]), "r"(a[1]), "r"(a[2]), "r"(a[3]), "r"(b[0]), "r"(b[1]));
}
__device__ __forceinline__ void ldsm_x4(uint32_t* r, uint32_t addr) {
    asm volatile("ldmatrix.sync.aligned.m8n8.x4.shared.b16 {%0,%1,%2,%3}, [%4];"
                 : "=r"(r[0]), "=r"(r[1]), "=r"(r[2]), "=r"(r[3]) : "r"(addr));
}
__device__ __forceinline__ void ldsm_x4_t(uint32_t* r, uint32_t addr) {
    asm volatile("ldmatrix.sync.aligned.m8n8.x4.trans.shared.b16 {%0,%1,%2,%3}, [%4];"
                 : "=r"(r[0]), "=r"(r[1]), "=r"(r[2]), "=r"(r[3]) : "r"(addr));
}
__device__ __forceinline__ void cp_async16(uint32_t s, const void* g) {
    asm volatile("cp.async.cg.shared.global [%0], [%1], 16;" :: "r"(s), "l"(g));
}
#define CP_COMMIT() asm volatile("cp.async.commit_group;" ::: "memory")
#define CP_WAIT(n)  asm volatile("cp.async.wait_group %0;" :: "n"(n) : "memory")

__device__ __forceinline__ uint32_t pack_bf16(float lo, float hi) {
    uint32_t r;
    asm("cvt.rn.bf16x2.f32 %0, %1, %2;" : "=r"(r) : "f"(hi), "f"(lo));
    return r;
}
__device__ __forceinline__ float bf16_round(float x) {
    return __bfloat162float(__float2bfloat16_rn(x));
}
// exp on the FMA pipe: valid for x <= 0; flushes below -87 (matches fp32 ref
// where exp(-1e5 - m) underflows to 0).
__device__ __forceinline__ float fast_exp(float x) {
    x = fmaxf(x, -87.0f);
    const float L2E = 1.4426950408889634f;
    float t = fmaf(x, L2E, 12582912.0f);
    float i = t - 12582912.0f;
    float f = fmaf(x, L2E, -i);
    float p =        1.3394582e-3f;
    p = fmaf(p, f, 9.6180217e-3f);
    p = fmaf(p, f, 5.5503368e-2f);
    p = fmaf(p, f, 2.4022652e-1f);
    p = fmaf(p, f, 6.9314718e-1f);
    p = fmaf(p, f, 1.0f);
    int e = (int)i;
    return __int_as_float((uint32_t)(e + 127) << 23) * p;
}

// ---------------------------------------------------------------------------
// fp32 -> (bf16 hi, bf16 lo) split
// ---------------------------------------------------------------------------
__global__ __launch_bounds__(256) void split_fp32(
    const float4* __restrict__ src,
    __nv_bfloat162* __restrict__ hi,
    __nv_bfloat162* __restrict__ lo)
{
    const size_t i = (size_t)blockIdx.x * 256 + threadIdx.x;
    const float4 v = src[i];
    __nv_bfloat16 hx = __float2bfloat16_rn(v.x);
    __nv_bfloat16 hy = __float2bfloat16_rn(v.y);
    __nv_bfloat16 hz = __float2bfloat16_rn(v.z);
    __nv_bfloat16 hw = __float2bfloat16_rn(v.w);
    hi[2 * i]     = __nv_bfloat162(hx, hy);
    hi[2 * i + 1] = __nv_bfloat162(hz, hw);
    lo[2 * i]     = __nv_bfloat162(__float2bfloat16_rn(v.x - __bfloat162float(hx)),
                                   __float2bfloat16_rn(v.y - __bfloat162float(hy)));
    lo[2 * i + 1] = __nv_bfloat162(__float2bfloat16_rn(v.z - __bfloat162float(hz)),
                                   __float2bfloat16_rn(v.w - __bfloat162float(hw)));
}

// ---------------------------------------------------------------------------
// Tensor GEMM via mma.sync: C = A * B^T (3-term bf16 split)
// Single __syncthreads per K-chunk; merged B hi/lo ldmatrix.x4.
// MODE 0: QKV -> scatter bf16 hi/lo (+bias). MODE 1: out = acc+bias+residual.
// ---------------------------------------------------------------------------
template <int MODE>
__global__ __launch_bounds__(256, 2) void tc_gemm(
    const __nv_bfloat16* __restrict__ Ahi, const __nv_bfloat16* __restrict__ Alo,
    const __nv_bfloat16* __restrict__ Bhi, const __nv_bfloat16* __restrict__ Blo,
    const float* __restrict__ bias,
    const float* __restrict__ residual,
    float* __restrict__ out)
{
    extern __shared__ char smem[];
    const uint32_t sbase = smem_u32(smem);
    const int tid  = threadIdx.x;
    const int wid  = tid >> 5;
    const int lane = tid & 31;
    const int wm   = wid >> 2;
    const int wn   = wid & 3;
    const int bm   = blockIdx.y * GBM;
    const int bn   = blockIdx.x * GBN;

    const __nv_bfloat16* Ah = Ahi + (size_t)bm * cH;
    const __nv_bfloat16* Al = Alo + (size_t)bm * cH;
    const __nv_bfloat16* Bh = Bhi + (size_t)bn * cH;
    const __nv_bfloat16* Bl = Blo + (size_t)bn * cH;

    float acc[4][4][4];
#pragma unroll
    for (int mi = 0; mi < 4; mi++)
#pragma unroll
        for (int nj = 0; nj < 4; nj++)
#pragma unroll
            for (int r = 0; r < 4; r++) acc[mi][nj][r] = 0.f;

    const int aRow = ((lane >> 3) & 1) * 8 + (lane & 7);
    const int aK   = (lane >> 4) * 8;
    const int bl15 = lane & 15;
    const int bN   = bl15 & 7;
    const int bK   = (bl15 >> 3) * 8;
    // merged hi/lo B load: lanes 0-15 -> Bhi tile, lanes 16-31 -> Blo tile
    const uint32_t bTile = (lane >= 16) ? (uint32_t)(3 * TILEB) : (uint32_t)(2 * TILEB);

    auto load_chunk = [&](uint32_t stage, int k0) {
#pragma unroll
        for (int it = 0; it < 2; ++it) {
            const int c   = tid + it * 256;
            const int row = c >> 2;
            const int kc  = c & 3;
            const uint32_t so = (uint32_t)(row * SKB + kc * 16);
            const size_t  go  = (size_t)row * cH + k0 + kc * 8;
            cp_async16(stage + 0 * TILEB + so, Ah + go);
            cp_async16(stage + 1 * TILEB + so, Al + go);
            cp_async16(stage + 2 * TILEB + so, Bh + go);
            cp_async16(stage + 3 * TILEB + so, Bl + go);
        }
    };

    constexpr int NCH = cH / GBK;
    load_chunk(sbase, 0);
    CP_COMMIT();

    for (int ch = 0; ch < NCH; ++ch) {
        CP_WAIT(0);            // own groups done
        __syncthreads();       // everyone's data visible; prev compute finished
        if (ch + 1 < NCH) {
            load_chunk(sbase + ((ch + 1) & 1) * STAGEB, (ch + 1) * GBK);
            CP_COMMIT();
        }
        const uint32_t st = sbase + (ch & 1) * STAGEB;
#pragma unroll
        for (int ks = 0; ks < 2; ++ks) {
            uint32_t ah[4][4], al[4][4];
#pragma unroll
            for (int mi = 0; mi < 4; ++mi) {
                const uint32_t ao =
                    (uint32_t)((wm * 64 + mi * 16 + aRow) * SKB + (ks * 16 + aK) * 2);
                ldsm_x4(ah[mi], st + 0 * TILEB + ao);
                ldsm_x4(al[mi], st + 1 * TILEB + ao);
            }
#pragma unroll
            for (int nj = 0; nj < 4; ++nj) {
                uint32_t bb[4];     // bb[0..1]=Bh frag, bb[2..3]=Bl frag
                const uint32_t bo =
                    (uint32_t)((wn * 32 + nj * 8 + bN) * SKB + (ks * 16 + bK) * 2);
                ldsm_x4(bb, st + bTile + bo);
#pragma unroll
                for (int mi = 0; mi < 4; ++mi) {
                    mma_bf16(acc[mi][nj], ah[mi], bb);
                    mma_bf16(acc[mi][nj], ah[mi], bb + 2);
                    mma_bf16(acc[mi][nj], al[mi], bb);
                }
            }
        }
    }

    const int l4 = lane >> 2;
    const int l2 = (lane & 3) * 2;
#pragma unroll
    for (int mi = 0; mi < 4; ++mi) {
#pragma unroll
        for (int nj = 0; nj < 4; ++nj) {
            const int colT = wn * 32 + nj * 8 + l2;
            const int o    = bn + colT;
            const float2 bia = *(const float2*)&bias[o];
#pragma unroll
            for (int half = 0; half < 2; ++half) {
                const int m = bm + wm * 64 + mi * 16 + l4 + half * 8;
                float vx = acc[mi][nj][half * 2 + 0] + bia.x;
                float vy = acc[mi][nj][half * 2 + 1] + bia.y;
                if (MODE == 0) {
                    const int nh = blockIdx.x / 3;
                    const int t  = blockIdx.x % 3;
                    __nv_bfloat16* dh = (t == 0) ? g_qh : (t == 1) ? g_kh : g_vh;
                    __nv_bfloat16* dl = (t == 0) ? g_ql : (t == 1) ? g_kl : g_vl;
                    const int b = m / cS, s = m % cS;
                    const size_t idx = ((size_t)(b * cNH + nh) * cS + s) * cHD + colT;
                    const float rx = bf16_round(vx), ry = bf16_round(vy);
                    *(uint32_t*)&dh[idx] = pack_bf16(vx, vy);
                    *(uint32_t*)&dl[idx] = pack_bf16(vx - rx, vy - ry);
                } else {
                    const size_t idx = (size_t)m * cH + o;
                    const float2 res = *(const float2*)&residual[idx];
                    float2 v; v.x = vx + res.x; v.y = vy + res.y;
                    *(float2*)&out[idx] = v;
                }
            }
        }
    }
}

// ---------------------------------------------------------------------------
// Attention via mma.sync: 64 q-rows/CTA, 4 warps; 32-row K/V tiles,
// double-buffered cp.async pipeline, single sync per tile.
// ---------------------------------------------------------------------------
__global__ __launch_bounds__(128) void attn_mma(const float* __restrict__ alibi)
{
    extern __shared__ char sm[];
    const uint32_t sb = smem_u32(sm);
    const int tid  = threadIdx.x;
    const int lane = tid & 31;
    const int w    = tid >> 5;
    const int qi   = (cS / ABQ - 1) - blockIdx.x;   // big tiles first
    const int bh   = blockIdx.y;
    const int b    = bh >> 5;
    const int nh   = bh & 31;
    const size_t hb = (size_t)bh * cS * cHD;
    const float inv_norm = 0.08838834764831845f;

    const int g    = lane >> 2;
    const int tig  = lane & 3;
    const int aRow = ((lane >> 3) & 1) * 8 + (lane & 7);
    const int aK   = (lane >> 4) * 8;
    const int bl15 = lane & 15;
    const int bN   = bl15 & 7;
    const int bK   = (bl15 >> 3) * 8;
    const uint32_t kSel = (lane >= 16) ? (uint32_t)ATILE : 0u;   // KL vs KH
    const int vRow = (lane & 7) + (((lane >> 3) & 1) << 3);
    const int vSel = lane >> 4;

    // ---- stage Q (64 rows) into stage-0 area: qh @ +0, ql @ +2*ATILE
#pragma unroll
    for (int i = 0; i < 8; i++) {
        const int id = tid + i * 128;
        const int r = id >> 4, c = id & 15;
        const size_t go = hb + (size_t)(qi * ABQ + r) * cHD + c * 8;
        const uint32_t so = (uint32_t)(r * ROWB + c * 16);
        cp_async16(sb + so, g_qh + go);
        cp_async16(sb + 2 * ATILE + so, g_ql + go);
    }
    CP_COMMIT(); CP_WAIT(0);
    __syncthreads();

    uint32_t qh[8][4], ql[8][4];
#pragma unroll
    for (int ks = 0; ks < 8; ks++) {
        const uint32_t ao = (uint32_t)((w * 16 + aRow) * ROWB + (ks * 16 + aK) * 2);
        ldsm_x4(qh[ks], sb + ao);
        ldsm_x4(ql[ks], sb + 2 * ATILE + ao);
    }
    __syncthreads();

    float ctx[16][4];
#pragma unroll
    for (int t = 0; t < 16; t++)
#pragma unroll
        for (int r = 0; r < 4; r++) ctx[t][r] = 0.f;
    float m1 = -INFINITY, m2 = -INFINITY, l1 = 0.f, l2 = 0.f;
    const int row1 = qi * ABQ + w * 16 + g;
    const int row2 = row1 + 8;

    // K/V tile loader (32 rows), stage in {0,1}
    auto load_kv = [&](int stage, int kt) {
        const uint32_t stb = sb + stage * ASTAGE;
#pragma unroll
        for (int i = 0; i < 4; i++) {
            const int id = tid + i * 128;          // 0..511
            const int r = id >> 4, c = id & 15;
            const size_t go = hb + (size_t)(kt * 32 + r) * cHD + c * 8;
            const uint32_t so = (uint32_t)(r * ROWB + c * 16);
            cp_async16(stb + 0 * ATILE + so, g_kh + go);
            cp_async16(stb + 1 * ATILE + so, g_kl + go);
            cp_async16(stb + 2 * ATILE + so, g_vh + go);
            cp_async16(stb + 3 * ATILE + so, g_vl + go);
        }
        if (tid < 32)
            ((float*)(sm + AOFF_ALI + stage * 128))[tid] =
                alibi[(size_t)bh * cS + kt * 32 + tid];
    };

    const int nkt = 2 * (qi + 1);     // 32-wide tiles covering [0, (qi+1)*64)
    load_kv(0, 0);
    CP_COMMIT();

    for (int kt = 0; kt < nkt; kt++) {
        CP_WAIT(0);
        __syncthreads();
        if (kt + 1 < nkt) { load_kv((kt + 1) & 1, kt + 1); CP_COMMIT(); }
        const uint32_t stb = sb + (kt & 1) * ASTAGE;
        const float* als = (const float*)(sm + AOFF_ALI + (kt & 1) * 128);

        // ---- S = Q K^T over 32 columns: 4 n8 tiles
        float sacc[4][4];
#pragma unroll
        for (int j = 0; j < 4; j++)
#pragma unroll
            for (int r = 0; r < 4; r++) sacc[j][r] = 0.f;

#pragma unroll
        for (int j = 0; j < 4; j++) {
#pragma unroll
            for (int ks = 0; ks < 8; ks++) {
                uint32_t kb[4];   // kb[0..1]=Kh frag, kb[2..3]=Kl frag
                const uint32_t bo =
                    (uint32_t)((j * 8 + bN) * ROWB + (ks * 16 + bK) * 2);
                ldsm_x4(kb, stb + kSel + bo);
                mma_bf16(sacc[j], qh[ks], kb);
                mma_bf16(sacc[j], qh[ks], kb + 2);
                mma_bf16(sacc[j], ql[ks], kb);
            }
        }

        // ---- scale + alibi + causal mask (only possible on last two tiles)
        const bool maskt = (kt >= 2 * qi);
#pragma unroll
        for (int j = 0; j < 4; j++) {
            const int c0 = j * 8 + tig * 2;
            const float a0 = als[c0], a1 = als[c0 + 1];
            sacc[j][0] = fmaf(sacc[j][0], inv_norm, a0);
            sacc[j][1] = fmaf(sacc[j][1], inv_norm, a1);
            sacc[j][2] = fmaf(sacc[j][2], inv_norm, a0);
            sacc[j][3] = fmaf(sacc[j][3], inv_norm, a1);
            if (maskt) {
                const int cg = kt * 32 + c0;
                if (cg     > row1) sacc[j][0] = -100000.0f;
                if (cg + 1 > row1) sacc[j][1] = -100000.0f;
                if (cg     > row2) sacc[j][2] = -100000.0f;
                if (cg + 1 > row2) sacc[j][3] = -100000.0f;
            }
        }

        // ---- online softmax (4-lane row groups)
        float mx1 = -INFINITY, mx2 = -INFINITY;
#pragma unroll
        for (int j = 0; j < 4; j++) {
            mx1 = fmaxf(mx1, fmaxf(sacc[j][0], sacc[j][1]));
            mx2 = fmaxf(mx2, fmaxf(sacc[j][2], sacc[j][3]));
        }
        mx1 = fmaxf(mx1, __shfl_xor_sync(0xffffffffu, mx1, 1));
        mx1 = fmaxf(mx1, __shfl_xor_sync(0xffffffffu, mx1, 2));
        mx2 = fmaxf(mx2, __shfl_xor_sync(0xffffffffu, mx2, 1));
        mx2 = fmaxf(mx2, __shfl_xor_sync(0xffffffffu, mx2, 2));

        const float mn1 = fmaxf(m1, mx1), mn2 = fmaxf(m2, mx2);
        const float sc1 = fast_exp(m1 - mn1), sc2 = fast_exp(m2 - mn2);
        float ls1 = 0.f, ls2 = 0.f;
#pragma unroll
        for (int j = 0; j < 4; j++) {
            sacc[j][0] = fast_exp(sacc[j][0] - mn1);
            sacc[j][1] = fast_exp(sacc[j][1] - mn1);
            sacc[j][2] = fast_exp(sacc[j][2] - mn2);
            sacc[j][3] = fast_exp(sacc[j][3] - mn2);
            ls1 += sacc[j][0] + sacc[j][1];
            ls2 += sacc[j][2] + sacc[j][3];
        }
        ls1 += __shfl_xor_sync(0xffffffffu, ls1, 1);
        ls1 += __shfl_xor_sync(0xffffffffu, ls1, 2);
        ls2 += __shfl_xor_sync(0xffffffffu, ls2, 1);
        ls2 += __shfl_xor_sync(0xffffffffu, ls2, 2);
        l1 = l1 * sc1 + ls1;  l2 = l2 * sc2 + ls2;
        m1 = mn1;             m2 = mn2;
#pragma unroll
        for (int t = 0; t < 16; t++) {
            ctx[t][0] *= sc1; ctx[t][1] *= sc1;
            ctx[t][2] *= sc2; ctx[t][3] *= sc2;
        }

        // ---- ctx += P V (2 k16 steps over the 32 kv rows)
#pragma unroll
        for (int ks2 = 0; ks2 < 2; ks2++) {
            const float p00 = sacc[2 * ks2][0],     p01 = sacc[2 * ks2][1];
            const float p02 = sacc[2 * ks2][2],     p03 = sacc[2 * ks2][3];
            const float p10 = sacc[2 * ks2 + 1][0], p11 = sacc[2 * ks2 + 1][1];
            const float p12 = sacc[2 * ks2 + 1][2], p13 = sacc[2 * ks2 + 1][3];
            uint32_t pah[4], pal[4];
            pah[0] = pack_bf16(p00, p01);
            pah[1] = pack_bf16(p02, p03);
            pah[2] = pack_bf16(p10, p11);
            pah[3] = pack_bf16(p12, p13);
            pal[0] = pack_bf16(p00 - bf16_round(p00), p01 - bf16_round(p01));
            pal[1] = pack_bf16(p02 - bf16_round(p02), p03 - bf16_round(p03));
            pal[2] = pack_bf16(p10 - bf16_round(p10), p11 - bf16_round(p11));
            pal[3] = pack_bf16(p12 - bf16_round(p12), p13 - bf16_round(p13));
#pragma unroll
            for (int p2 = 0; p2 < 8; p2++) {
                uint32_t vbh[4], vbl[4];
                const uint32_t vo =
                    (uint32_t)((ks2 * 16 + vRow) * ROWB + (p2 * 16 + vSel * 8) * 2);
                ldsm_x4_t(vbh, stb + 2 * ATILE + vo);
                ldsm_x4_t(vbl, stb + 3 * ATILE + vo);
                mma_bf16(ctx[2 * p2],     pah, vbh);
                mma_bf16(ctx[2 * p2],     pah, vbl);
                mma_bf16(ctx[2 * p2],     pal, vbh);
                mma_bf16(ctx[2 * p2 + 1], pah, vbh + 2);
                mma_bf16(ctx[2 * p2 + 1], pah, vbl + 2);
                mma_bf16(ctx[2 * p2 + 1], pal, vbh + 2);
            }
        }
    }

    // ---- epilogue: normalize, split to bf16 hi/lo ctx
    const float inv1 = 1.0f / l1, inv2 = 1.0f / l2;
    const size_t o1 = (size_t)(b * cS + row1) * cH + nh * cHD;
    const size_t o2 = (size_t)(b * cS + row2) * cH + nh * cHD;
#pragma unroll
    for (int t = 0; t < 16; t++) {
        const int d = t * 8 + tig * 2;
        const float v0 = ctx[t][0] * inv1, v1 = ctx[t][1] * inv1;
        const float v2 = ctx[t][2] * inv2, v3 = ctx[t][3] * inv2;
        *(uint32_t*)&g_ctx_hi[o1 + d] = pack_bf16(v0, v1);
        *(uint32_t*)&g_ctx_lo[o1 + d] = pack_bf16(v0 - bf16_round(v0), v1 - bf16_round(v1));
        *(uint32_t*)&g_ctx_hi[o2 + d] = pack_bf16(v2, v3);
        *(uint32_t*)&g_ctx_lo[o2 + d] = pack_bf16(v2 - bf16_round(v2), v3 - bf16_round(v3));
    }
}

// ---------------------------------------------------------------------------
// Launch
// ---------------------------------------------------------------------------
extern "C" void kernel_launch(void* const* d_in, const int* in_sizes, int n_in,
                              void* d_out, int out_size)
{
    (void)in_sizes; (void)n_in; (void)out_size;
    const float* hidden   = (const float*)d_in[0];
    const float* residual = (const float*)d_in[1];
    const float* alibi    = (const float*)d_in[2];
    const float* W_qkv    = (const float*)d_in[4];
    const float* b_qkv    = (const float*)d_in[5];
    const float* W_dense  = (const float*)d_in[6];
    const float* b_dense  = (const float*)d_in[7];
    float* out = (float*)d_out;

    cudaFuncSetAttribute(tc_gemm<0>, cudaFuncAttributeMaxDynamicSharedMemorySize, GEMM_SMEM);
    cudaFuncSetAttribute(tc_gemm<1>, cudaFuncAttributeMaxDynamicSharedMemorySize, GEMM_SMEM);
    cudaFuncSetAttribute(attn_mma,  cudaFuncAttributeMaxDynamicSharedMemorySize, ATTN_SMEM);

    __nv_bfloat16 *hid_hi, *hid_lo, *wq_hi, *wq_lo, *wd_hi, *wd_lo, *cx_hi, *cx_lo;
    cudaGetSymbolAddress((void**)&hid_hi, g_hid_hi);
    cudaGetSymbolAddress((void**)&hid_lo, g_hid_lo);
    cudaGetSymbolAddress((void**)&wq_hi,  g_wqkv_hi);
    cudaGetSymbolAddress((void**)&wq_lo,  g_wqkv_lo);
    cudaGetSymbolAddress((void**)&wd_hi,  g_wd_hi);
    cudaGetSymbolAddress((void**)&wd_lo,  g_wd_lo);
    cudaGetSymbolAddress((void**)&cx_hi,  g_ctx_hi);
    cudaGetSymbolAddress((void**)&cx_lo,  g_ctx_lo);

    // 0) fp32 -> bf16 hi/lo splits
    split_fp32<<<(cM * cH) / 1024, 256>>>((const float4*)hidden,
        (__nv_bfloat162*)hid_hi, (__nv_bfloat162*)hid_lo);
    split_fp32<<<(cQKVN * cH) / 1024, 256>>>((const float4*)W_qkv,
        (__nv_bfloat162*)wq_hi, (__nv_bfloat162*)wq_lo);
    split_fp32<<<(cH * cH) / 1024, 256>>>((const float4*)W_dense,
        (__nv_bfloat162*)wd_hi, (__nv_bfloat162*)wd_lo);

    // 1) QKV GEMM -> q/k/v bf16 hi/lo
    tc_gemm<0><<<dim3(cQKVN / GBN, cM / GBM), 256, GEMM_SMEM>>>(
        hid_hi, hid_lo, wq_hi, wq_lo, b_qkv, nullptr, nullptr);

    // 2) attention (tensor) -> ctx bf16 hi/lo
    attn_mma<<<dim3(cS / ABQ, cB * cNH), 128, ATTN_SMEM>>>(alibi);

    // 3) dense GEMM + bias + residual -> out
    tc_gemm<1><<<dim3(cH / GBN, cM / GBM), 256, GEMM_SMEM>>>(
        cx_hi, cx_lo, wd_hi, wd_lo, b_dense, residual, out);
}

// round 11
// speedup vs baseline: 4.5314x; 1.4464x over previous
#include <cuda_runtime.h>
#include <cuda_fp16.h>
#include <math.h>
#include <cstdint>

// ---------------------------------------------------------------------------
// Problem constants
// ---------------------------------------------------------------------------
namespace {
constexpr int cB  = 2;
constexpr int cS  = 2048;
constexpr int cH  = 4096;
constexpr int cNH = 32;
constexpr int cHD = 128;
constexpr int cM  = cB * cS;      // 4096
constexpr int cQKVN = 3 * cH;     // 12288

// GEMM tiling (mma.sync path)
constexpr int GBM = 128, GBN = 128, GBK = 32;
constexpr int SKB   = 80;                 // smem row stride bytes
constexpr int TILEB = GBM * SKB;          // 10240
constexpr int STAGE4 = 4 * TILEB;         // Ah,Al,Bh,Bl (3-term kernel)
constexpr int SMEM_QK = 2 * STAGE4;       // 81920
constexpr int STAGE2 = 2 * TILEB;         // Ah,Bh (1-term kernels)
constexpr int SMEM_1T = 2 * STAGE2;       // 40960

// Attention: q-tile 64 rows, k-tile 32 rows, double-buffered, 3 tiles/stage
constexpr int ABQ = 64;
constexpr int ROWB = 272;                 // 128 fp16 + pad = 272 bytes
constexpr int ATILE = 32 * ROWB;          // 8704
constexpr int ASTAGE = 3 * ATILE;         // KH,KL,VH = 26112
constexpr int AOFF_ALI = 2 * ASTAGE;      // 52224
constexpr int ATTN_SMEM = AOFF_ALI + 256; // 52480
}

// ---------------------------------------------------------------------------
// Scratch (__device__ globals)
// ---------------------------------------------------------------------------
__device__ __half g_qh[(size_t)cB * cNH * cS * cHD];
__device__ __half g_ql[(size_t)cB * cNH * cS * cHD];
__device__ __half g_kh[(size_t)cB * cNH * cS * cHD];
__device__ __half g_kl[(size_t)cB * cNH * cS * cHD];
__device__ __half g_vh[(size_t)cB * cNH * cS * cHD];

__device__ __half g_hid_hi[(size_t)cM * cH];
__device__ __half g_hid_lo[(size_t)cM * cH];
__device__ __half g_wqkv_hi[(size_t)cQKVN * cH];
__device__ __half g_wqkv_lo[(size_t)cQKVN * cH];
__device__ __half g_wd_hi[(size_t)cH * cH];
__device__ __half g_ctx_hi[(size_t)cM * cH];

// ---------------------------------------------------------------------------
// PTX helpers — non-arch-specific only (mma.sync / ldmatrix / cp.async)
// ---------------------------------------------------------------------------
__device__ __forceinline__ uint32_t smem_u32(const void* p) {
    uint32_t a;
    asm("{ .reg .u64 t; cvta.to.shared.u64 t, %1; cvt.u32.u64 %0, t; }" : "=r"(a) : "l"(p));
    return a;
}
__device__ __forceinline__ void mma_f16(float* c, const uint32_t* a, const uint32_t* b) {
    asm volatile(
        "mma.sync.aligned.m16n8k16.row.col.f32.f16.f16.f32 "
        "{%0,%1,%2,%3}, {%4,%5,%6,%7}, {%8,%9}, {%0,%1,%2,%3};"
        : "+f"(c[0]), "+f"(c[1]), "+f"(c[2]), "+f"(c[3])
        : "r"(a[0]), "r"(a[1]), "r"(a[2]), "r"(a[3]), "r"(b[0]), "r"(b[1]));
}
__device__ __forceinline__ void ldsm_x4(uint32_t* r, uint32_t addr) {
    asm volatile("ldmatrix.sync.aligned.m8n8.x4.shared.b16 {%0,%1,%2,%3}, [%4];"
                 : "=r"(r[0]), "=r"(r[1]), "=r"(r[2]), "=r"(r[3]) : "r"(addr));
}
__device__ __forceinline__ void ldsm_x4_t(uint32_t* r, uint32_t addr) {
    asm volatile("ldmatrix.sync.aligned.m8n8.x4.trans.shared.b16 {%0,%1,%2,%3}, [%4];"
                 : "=r"(r[0]), "=r"(r[1]), "=r"(r[2]), "=r"(r[3]) : "r"(addr));
}
__device__ __forceinline__ void cp_async16(uint32_t s, const void* g) {
    asm volatile("cp.async.cg.shared.global [%0], [%1], 16;" :: "r"(s), "l"(g));
}
#define CP_COMMIT() asm volatile("cp.async.commit_group;" ::: "memory")
#define CP_WAIT(n)  asm volatile("cp.async.wait_group %0;" :: "n"(n) : "memory")

__device__ __forceinline__ uint32_t pack_f16(float lo, float hi) {
    uint32_t r;
    asm("cvt.rn.f16x2.f32 %0, %1, %2;" : "=r"(r) : "f"(hi), "f"(lo));
    return r;
}
__device__ __forceinline__ float f16_round(float x) {
    return __half2float(__float2half_rn(x));
}
// exp on the FMA pipe: valid for x <= 0; flushes below -87.
__device__ __forceinline__ float fast_exp(float x) {
    x = fmaxf(x, -87.0f);
    const float L2E = 1.4426950408889634f;
    float t = fmaf(x, L2E, 12582912.0f);
    float i = t - 12582912.0f;
    float f = fmaf(x, L2E, -i);
    float p =        1.3394582e-3f;
    p = fmaf(p, f, 9.6180217e-3f);
    p = fmaf(p, f, 5.5503368e-2f);
    p = fmaf(p, f, 2.4022652e-1f);
    p = fmaf(p, f, 6.9314718e-1f);
    p = fmaf(p, f, 1.0f);
    int e = (int)i;
    return __int_as_float((uint32_t)(e + 127) << 23) * p;
}

// ---------------------------------------------------------------------------
// fp32 -> (fp16 hi, fp16 lo) split; and hi-only variant
// ---------------------------------------------------------------------------
__global__ __launch_bounds__(256) void split_fp32(
    const float4* __restrict__ src, __half2* __restrict__ hi, __half2* __restrict__ lo)
{
    const size_t i = (size_t)blockIdx.x * 256 + threadIdx.x;
    const float4 v = src[i];
    __half hx = __float2half_rn(v.x);
    __half hy = __float2half_rn(v.y);
    __half hz = __float2half_rn(v.z);
    __half hw = __float2half_rn(v.w);
    hi[2 * i]     = __halves2half2(hx, hy);
    hi[2 * i + 1] = __halves2half2(hz, hw);
    lo[2 * i]     = __halves2half2(__float2half_rn(v.x - __half2float(hx)),
                                   __float2half_rn(v.y - __half2float(hy)));
    lo[2 * i + 1] = __halves2half2(__float2half_rn(v.z - __half2float(hz)),
                                   __float2half_rn(v.w - __half2float(hw)));
}
__global__ __launch_bounds__(256) void split_fp32_hi(
    const float4* __restrict__ src, __half2* __restrict__ hi)
{
    const size_t i = (size_t)blockIdx.x * 256 + threadIdx.x;
    const float4 v = src[i];
    hi[2 * i]     = __halves2half2(__float2half_rn(v.x), __float2half_rn(v.y));
    hi[2 * i + 1] = __halves2half2(__float2half_rn(v.z), __float2half_rn(v.w));
}

// ---------------------------------------------------------------------------
// 3-term GEMM (fp16 split): Q/K part of QKV.
// grid (64, 32): nh = bx>>1, t = bx&1 (0=Q, 1=K). Output: hi/lo fp16 scatter.
// ---------------------------------------------------------------------------
__global__ __launch_bounds__(256, 2) void tc_gemm_qk(
    const __half* __restrict__ Ahi, const __half* __restrict__ Alo,
    const __half* __restrict__ Bhi, const __half* __restrict__ Blo,
    const float* __restrict__ bias)
{
    extern __shared__ char smem[];
    const uint32_t sbase = smem_u32(smem);
    const int tid  = threadIdx.x;
    const int wid  = tid >> 5;
    const int lane = tid & 31;
    const int wm   = wid >> 2;
    const int wn   = wid & 3;
    const int bm   = blockIdx.y * GBM;
    const int nh   = blockIdx.x >> 1;
    const int t    = blockIdx.x & 1;
    const int obase = nh * 384 + t * 128;

    const __half* Ah = Ahi + (size_t)bm * cH;
    const __half* Al = Alo + (size_t)bm * cH;
    const __half* Bh = Bhi + (size_t)obase * cH;
    const __half* Bl = Blo + (size_t)obase * cH;

    float acc[4][4][4];
#pragma unroll
    for (int mi = 0; mi < 4; mi++)
#pragma unroll
        for (int nj = 0; nj < 4; nj++)
#pragma unroll
            for (int r = 0; r < 4; r++) acc[mi][nj][r] = 0.f;

    const int aRow = ((lane >> 3) & 1) * 8 + (lane & 7);
    const int aK   = (lane >> 4) * 8;
    const int bl15 = lane & 15;
    const int bN   = bl15 & 7;
    const int bK   = (bl15 >> 3) * 8;
    const uint32_t bTile = (lane >= 16) ? (uint32_t)(3 * TILEB) : (uint32_t)(2 * TILEB);

    auto load_chunk = [&](uint32_t stage, int k0) {
#pragma unroll
        for (int it = 0; it < 2; ++it) {
            const int c   = tid + it * 256;
            const int row = c >> 2;
            const int kc  = c & 3;
            const uint32_t so = (uint32_t)(row * SKB + kc * 16);
            const size_t  go  = (size_t)row * cH + k0 + kc * 8;
            cp_async16(stage + 0 * TILEB + so, Ah + go);
            cp_async16(stage + 1 * TILEB + so, Al + go);
            cp_async16(stage + 2 * TILEB + so, Bh + go);
            cp_async16(stage + 3 * TILEB + so, Bl + go);
        }
    };

    constexpr int NCH = cH / GBK;
    load_chunk(sbase, 0);
    CP_COMMIT();

    for (int ch = 0; ch < NCH; ++ch) {
        CP_WAIT(0);
        __syncthreads();
        if (ch + 1 < NCH) {
            load_chunk(sbase + ((ch + 1) & 1) * STAGE4, (ch + 1) * GBK);
            CP_COMMIT();
        }
        const uint32_t st = sbase + (ch & 1) * STAGE4;
#pragma unroll
        for (int ks = 0; ks < 2; ++ks) {
            uint32_t ah[4][4], al[4][4];
#pragma unroll
            for (int mi = 0; mi < 4; ++mi) {
                const uint32_t ao =
                    (uint32_t)((wm * 64 + mi * 16 + aRow) * SKB + (ks * 16 + aK) * 2);
                ldsm_x4(ah[mi], st + 0 * TILEB + ao);
                ldsm_x4(al[mi], st + 1 * TILEB + ao);
            }
#pragma unroll
            for (int nj = 0; nj < 4; ++nj) {
                uint32_t bb[4];     // [0..1]=Bh frag, [2..3]=Bl frag (lane-merged)
                const uint32_t bo =
                    (uint32_t)((wn * 32 + nj * 8 + bN) * SKB + (ks * 16 + bK) * 2);
                ldsm_x4(bb, st + bTile + bo);
#pragma unroll
                for (int mi = 0; mi < 4; ++mi) {
                    mma_f16(acc[mi][nj], ah[mi], bb);
                    mma_f16(acc[mi][nj], ah[mi], bb + 2);
                    mma_f16(acc[mi][nj], al[mi], bb);
                }
            }
        }
    }

    const int l4 = lane >> 2;
    const int l2 = (lane & 3) * 2;
    __half* dh = t ? g_kh : g_qh;
    __half* dl = t ? g_kl : g_ql;
#pragma unroll
    for (int mi = 0; mi < 4; ++mi) {
#pragma unroll
        for (int nj = 0; nj < 4; ++nj) {
            const int colT = wn * 32 + nj * 8 + l2;
            const float2 bia = *(const float2*)&bias[obase + colT];
#pragma unroll
            for (int half = 0; half < 2; ++half) {
                const int m = bm + wm * 64 + mi * 16 + l4 + half * 8;
                const float vx = acc[mi][nj][half * 2 + 0] + bia.x;
                const float vy = acc[mi][nj][half * 2 + 1] + bia.y;
                const int b = m / cS, s = m % cS;
                const size_t idx = ((size_t)(b * cNH + nh) * cS + s) * cHD + colT;
                *(uint32_t*)&dh[idx] = pack_f16(vx, vy);
                *(uint32_t*)&dl[idx] = pack_f16(vx - f16_round(vx), vy - f16_round(vy));
            }
        }
    }
}

// ---------------------------------------------------------------------------
// 1-term GEMM (plain fp16): MODE 2 = V part of QKV (scatter vh), MODE 1 = dense.
// ---------------------------------------------------------------------------
template <int MODE>
__global__ __launch_bounds__(256, 2) void tc_gemm_1t(
    const __half* __restrict__ Ahi, const __half* __restrict__ Bhi,
    const float* __restrict__ bias,
    const float* __restrict__ residual,
    float* __restrict__ out)
{
    extern __shared__ char smem[];
    const uint32_t sbase = smem_u32(smem);
    const int tid  = threadIdx.x;
    const int wid  = tid >> 5;
    const int lane = tid & 31;
    const int wm   = wid >> 2;
    const int wn   = wid & 3;
    const int bm   = blockIdx.y * GBM;
    const int obase = (MODE == 2) ? ((int)blockIdx.x * 384 + 256) : ((int)blockIdx.x * 128);

    const __half* Ah = Ahi + (size_t)bm * cH;
    const __half* Bh = Bhi + (size_t)obase * cH;

    float acc[4][4][4];
#pragma unroll
    for (int mi = 0; mi < 4; mi++)
#pragma unroll
        for (int nj = 0; nj < 4; nj++)
#pragma unroll
            for (int r = 0; r < 4; r++) acc[mi][nj][r] = 0.f;

    const int aRow = ((lane >> 3) & 1) * 8 + (lane & 7);
    const int aK   = (lane >> 4) * 8;
    const int bRow = ((lane >> 4) << 3) + (lane & 7);   // n-row within 16
    const int bK   = ((lane >> 3) & 1) * 8;

    auto load_chunk = [&](uint32_t stage, int k0) {
#pragma unroll
        for (int it = 0; it < 2; ++it) {
            const int c   = tid + it * 256;
            const int row = c >> 2;
            const int kc  = c & 3;
            const uint32_t so = (uint32_t)(row * SKB + kc * 16);
            const size_t  go  = (size_t)row * cH + k0 + kc * 8;
            cp_async16(stage + 0 * TILEB + so, Ah + go);
            cp_async16(stage + 1 * TILEB + so, Bh + go);
        }
    };

    constexpr int NCH = cH / GBK;
    load_chunk(sbase, 0);
    CP_COMMIT();

    for (int ch = 0; ch < NCH; ++ch) {
        CP_WAIT(0);
        __syncthreads();
        if (ch + 1 < NCH) {
            load_chunk(sbase + ((ch + 1) & 1) * STAGE2, (ch + 1) * GBK);
            CP_COMMIT();
        }
        const uint32_t st = sbase + (ch & 1) * STAGE2;
#pragma unroll
        for (int ks = 0; ks < 2; ++ks) {
            uint32_t ah[4][4];
#pragma unroll
            for (int mi = 0; mi < 4; ++mi) {
                const uint32_t ao =
                    (uint32_t)((wm * 64 + mi * 16 + aRow) * SKB + (ks * 16 + aK) * 2);
                ldsm_x4(ah[mi], st + ao);
            }
#pragma unroll
            for (int nj2 = 0; nj2 < 2; ++nj2) {
                uint32_t bb[4];     // [0..1]=nj even frag, [2..3]=nj odd frag
                const uint32_t bo =
                    (uint32_t)((wn * 32 + nj2 * 16 + bRow) * SKB + (ks * 16 + bK) * 2);
                ldsm_x4(bb, st + TILEB + bo);
#pragma unroll
                for (int mi = 0; mi < 4; ++mi) {
                    mma_f16(acc[mi][2 * nj2],     ah[mi], bb);
                    mma_f16(acc[mi][2 * nj2 + 1], ah[mi], bb + 2);
                }
            }
        }
    }

    const int l4 = lane >> 2;
    const int l2 = (lane & 3) * 2;
#pragma unroll
    for (int mi = 0; mi < 4; ++mi) {
#pragma unroll
        for (int nj = 0; nj < 4; ++nj) {
            const int colT = wn * 32 + nj * 8 + l2;
            const int o    = obase + colT;
            const float2 bia = *(const float2*)&bias[o];
#pragma unroll
            for (int half = 0; half < 2; ++half) {
                const int m = bm + wm * 64 + mi * 16 + l4 + half * 8;
                const float vx = acc[mi][nj][half * 2 + 0] + bia.x;
                const float vy = acc[mi][nj][half * 2 + 1] + bia.y;
                if (MODE == 2) {
                    const int b = m / cS, s = m % cS;
                    const size_t idx =
                        ((size_t)(b * cNH + blockIdx.x) * cS + s) * cHD + colT;
                    *(uint32_t*)&g_vh[idx] = pack_f16(vx, vy);
                } else {
                    const size_t idx = (size_t)m * cH + o;
                    const float2 res = *(const float2*)&residual[idx];
                    float2 v; v.x = vx + res.x; v.y = vy + res.y;
                    *(float2*)&out[idx] = v;
                }
            }
        }
    }
}

// ---------------------------------------------------------------------------
// Attention: 64 q-rows/CTA, 4 warps; 32-row K/V tiles double-buffered.
// QK = 3-term fp16 (protected path); PV = 1-term fp16.
// ---------------------------------------------------------------------------
__global__ __launch_bounds__(128) void attn_mma(const float* __restrict__ alibi)
{
    extern __shared__ char sm[];
    const uint32_t sb = smem_u32(sm);
    const int tid  = threadIdx.x;
    const int lane = tid & 31;
    const int w    = tid >> 5;
    const int qi   = (cS / ABQ - 1) - blockIdx.x;   // big tiles first
    const int bh   = blockIdx.y;
    const int b    = bh >> 5;
    const int nh   = bh & 31;
    const size_t hb = (size_t)bh * cS * cHD;
    const float inv_norm = 0.08838834764831845f;

    const int g    = lane >> 2;
    const int tig  = lane & 3;
    const int aRow = ((lane >> 3) & 1) * 8 + (lane & 7);
    const int aK   = (lane >> 4) * 8;
    const int bl15 = lane & 15;
    const int bN   = bl15 & 7;
    const int bK   = (bl15 >> 3) * 8;
    const uint32_t kSel = (lane >= 16) ? (uint32_t)ATILE : 0u;   // KL vs KH
    const int vRow = (lane & 7) + (((lane >> 3) & 1) << 3);
    const int vSel = lane >> 4;

    // ---- stage Q (64 rows): qh @ +0, ql @ +ATILE*? use KH/KL slots
#pragma unroll
    for (int i = 0; i < 8; i++) {
        const int id = tid + i * 128;
        const int r = id >> 4, c = id & 15;
        const size_t go = hb + (size_t)(qi * ABQ + r) * cHD + c * 8;
        const uint32_t so = (uint32_t)(r * ROWB + c * 16);
        cp_async16(sb + so, g_qh + go);           // rows 0..31 in KH slot, 32..63 spill into KL
        cp_async16(sb + ASTAGE + so, g_ql + go);  // lo in stage-1 area
    }
    CP_COMMIT(); CP_WAIT(0);
    __syncthreads();

    uint32_t qh[8][4], ql[8][4];
#pragma unroll
    for (int ks = 0; ks < 8; ks++) {
        const uint32_t ao = (uint32_t)((w * 16 + aRow) * ROWB + (ks * 16 + aK) * 2);
        ldsm_x4(qh[ks], sb + ao);
        ldsm_x4(ql[ks], sb + ASTAGE + ao);
    }
    __syncthreads();

    float ctx[16][4];
#pragma unroll
    for (int t = 0; t < 16; t++)
#pragma unroll
        for (int r = 0; r < 4; r++) ctx[t][r] = 0.f;
    float m1 = -INFINITY, m2 = -INFINITY, l1 = 0.f, l2 = 0.f;
    const int row1 = qi * ABQ + w * 16 + g;
    const int row2 = row1 + 8;

    auto load_kv = [&](int stage, int kt) {
        const uint32_t stb = sb + stage * ASTAGE;
#pragma unroll
        for (int i = 0; i < 4; i++) {
            const int id = tid + i * 128;
            const int r = id >> 4, c = id & 15;
            const size_t go = hb + (size_t)(kt * 32 + r) * cHD + c * 8;
            const uint32_t so = (uint32_t)(r * ROWB + c * 16);
            cp_async16(stb + 0 * ATILE + so, g_kh + go);
            cp_async16(stb + 1 * ATILE + so, g_kl + go);
            cp_async16(stb + 2 * ATILE + so, g_vh + go);
        }
        if (tid < 32)
            ((float*)(sm + AOFF_ALI + stage * 128))[tid] =
                alibi[(size_t)bh * cS + kt * 32 + tid];
    };

    const int nkt = 2 * (qi + 1);
    load_kv(0, 0);
    CP_COMMIT();

    for (int kt = 0; kt < nkt; kt++) {
        CP_WAIT(0);
        __syncthreads();
        if (kt + 1 < nkt) { load_kv((kt + 1) & 1, kt + 1); CP_COMMIT(); }
        const uint32_t stb = sb + (kt & 1) * ASTAGE;
        const float* als = (const float*)(sm + AOFF_ALI + (kt & 1) * 128);

        // ---- S = Q K^T (3-term)
        float sacc[4][4];
#pragma unroll
        for (int j = 0; j < 4; j++)
#pragma unroll
            for (int r = 0; r < 4; r++) sacc[j][r] = 0.f;

#pragma unroll
        for (int j = 0; j < 4; j++) {
#pragma unroll
            for (int ks = 0; ks < 8; ks++) {
                uint32_t kb[4];   // [0..1]=Kh, [2..3]=Kl (lane-merged)
                const uint32_t bo =
                    (uint32_t)((j * 8 + bN) * ROWB + (ks * 16 + bK) * 2);
                ldsm_x4(kb, stb + kSel + bo);
                mma_f16(sacc[j], qh[ks], kb);
                mma_f16(sacc[j], qh[ks], kb + 2);
                mma_f16(sacc[j], ql[ks], kb);
            }
        }

        // ---- scale + alibi + causal mask (only last two tiles can mask)
        const bool maskt = (kt >= 2 * qi);
#pragma unroll
        for (int j = 0; j < 4; j++) {
            const int c0 = j * 8 + tig * 2;
            const float a0 = als[c0], a1 = als[c0 + 1];
            sacc[j][0] = fmaf(sacc[j][0], inv_norm, a0);
            sacc[j][1] = fmaf(sacc[j][1], inv_norm, a1);
            sacc[j][2] = fmaf(sacc[j][2], inv_norm, a0);
            sacc[j][3] = fmaf(sacc[j][3], inv_norm, a1);
            if (maskt) {
                const int cg = kt * 32 + c0;
                if (cg     > row1) sacc[j][0] = -100000.0f;
                if (cg + 1 > row1) sacc[j][1] = -100000.0f;
                if (cg     > row2) sacc[j][2] = -100000.0f;
                if (cg + 1 > row2) sacc[j][3] = -100000.0f;
            }
        }

        // ---- online softmax
        float mx1 = -INFINITY, mx2 = -INFINITY;
#pragma unroll
        for (int j = 0; j < 4; j++) {
            mx1 = fmaxf(mx1, fmaxf(sacc[j][0], sacc[j][1]));
            mx2 = fmaxf(mx2, fmaxf(sacc[j][2], sacc[j][3]));
        }
        mx1 = fmaxf(mx1, __shfl_xor_sync(0xffffffffu, mx1, 1));
        mx1 = fmaxf(mx1, __shfl_xor_sync(0xffffffffu, mx1, 2));
        mx2 = fmaxf(mx2, __shfl_xor_sync(0xffffffffu, mx2, 1));
        mx2 = fmaxf(mx2, __shfl_xor_sync(0xffffffffu, mx2, 2));

        const float mn1 = fmaxf(m1, mx1), mn2 = fmaxf(m2, mx2);
        const float sc1 = fast_exp(m1 - mn1), sc2 = fast_exp(m2 - mn2);
        float ls1 = 0.f, ls2 = 0.f;
#pragma unroll
        for (int j = 0; j < 4; j++) {
            sacc[j][0] = fast_exp(sacc[j][0] - mn1);
            sacc[j][1] = fast_exp(sacc[j][1] - mn1);
            sacc[j][2] = fast_exp(sacc[j][2] - mn2);
            sacc[j][3] = fast_exp(sacc[j][3] - mn2);
            ls1 += sacc[j][0] + sacc[j][1];
            ls2 += sacc[j][2] + sacc[j][3];
        }
        ls1 += __shfl_xor_sync(0xffffffffu, ls1, 1);
        ls1 += __shfl_xor_sync(0xffffffffu, ls1, 2);
        ls2 += __shfl_xor_sync(0xffffffffu, ls2, 1);
        ls2 += __shfl_xor_sync(0xffffffffu, ls2, 2);
        l1 = l1 * sc1 + ls1;  l2 = l2 * sc2 + ls2;
        m1 = mn1;             m2 = mn2;
#pragma unroll
        for (int t = 0; t < 16; t++) {
            ctx[t][0] *= sc1; ctx[t][1] *= sc1;
            ctx[t][2] *= sc2; ctx[t][3] *= sc2;
        }

        // ---- ctx += P V (1-term: Ph x Vh)
#pragma unroll
        for (int ks2 = 0; ks2 < 2; ks2++) {
            uint32_t pah[4];
            pah[0] = pack_f16(sacc[2 * ks2][0],     sacc[2 * ks2][1]);
            pah[1] = pack_f16(sacc[2 * ks2][2],     sacc[2 * ks2][3]);
            pah[2] = pack_f16(sacc[2 * ks2 + 1][0], sacc[2 * ks2 + 1][1]);
            pah[3] = pack_f16(sacc[2 * ks2 + 1][2], sacc[2 * ks2 + 1][3]);
#pragma unroll
            for (int p2 = 0; p2 < 8; p2++) {
                uint32_t vbh[4];
                const uint32_t vo =
                    (uint32_t)((ks2 * 16 + vRow) * ROWB + (p2 * 16 + vSel * 8) * 2);
                ldsm_x4_t(vbh, stb + 2 * ATILE + vo);
                mma_f16(ctx[2 * p2],     pah, vbh);
                mma_f16(ctx[2 * p2 + 1], pah, vbh + 2);
            }
        }
    }

    // ---- epilogue: normalize, fp16 ctx (hi only)
    const float inv1 = 1.0f / l1, inv2 = 1.0f / l2;
    const size_t o1 = (size_t)(b * cS + row1) * cH + nh * cHD;
    const size_t o2 = (size_t)(b * cS + row2) * cH + nh * cHD;
#pragma unroll
    for (int t = 0; t < 16; t++) {
        const int d = t * 8 + tig * 2;
        *(uint32_t*)&g_ctx_hi[o1 + d] = pack_f16(ctx[t][0] * inv1, ctx[t][1] * inv1);
        *(uint32_t*)&g_ctx_hi[o2 + d] = pack_f16(ctx[t][2] * inv2, ctx[t][3] * inv2);
    }
}

// ---------------------------------------------------------------------------
// Launch
// ---------------------------------------------------------------------------
extern "C" void kernel_launch(void* const* d_in, const int* in_sizes, int n_in,
                              void* d_out, int out_size)
{
    (void)in_sizes; (void)n_in; (void)out_size;
    const float* hidden   = (const float*)d_in[0];
    const float* residual = (const float*)d_in[1];
    const float* alibi    = (const float*)d_in[2];
    const float* W_qkv    = (const float*)d_in[4];
    const float* b_qkv    = (const float*)d_in[5];
    const float* W_dense  = (const float*)d_in[6];
    const float* b_dense  = (const float*)d_in[7];
    float* out = (float*)d_out;

    cudaFuncSetAttribute(tc_gemm_qk,    cudaFuncAttributeMaxDynamicSharedMemorySize, SMEM_QK);
    cudaFuncSetAttribute(tc_gemm_1t<2>, cudaFuncAttributeMaxDynamicSharedMemorySize, SMEM_1T);
    cudaFuncSetAttribute(tc_gemm_1t<1>, cudaFuncAttributeMaxDynamicSharedMemorySize, SMEM_1T);
    cudaFuncSetAttribute(attn_mma,      cudaFuncAttributeMaxDynamicSharedMemorySize, ATTN_SMEM);

    __half *hid_hi, *hid_lo, *wq_hi, *wq_lo, *wd_hi, *cx_hi;
    cudaGetSymbolAddress((void**)&hid_hi, g_hid_hi);
    cudaGetSymbolAddress((void**)&hid_lo, g_hid_lo);
    cudaGetSymbolAddress((void**)&wq_hi,  g_wqkv_hi);
    cudaGetSymbolAddress((void**)&wq_lo,  g_wqkv_lo);
    cudaGetSymbolAddress((void**)&wd_hi,  g_wd_hi);
    cudaGetSymbolAddress((void**)&cx_hi,  g_ctx_hi);

    // 0) fp32 -> fp16 splits
    split_fp32<<<(cM * cH) / 1024, 256>>>((const float4*)hidden,
        (__half2*)hid_hi, (__half2*)hid_lo);
    split_fp32<<<(cQKVN * cH) / 1024, 256>>>((const float4*)W_qkv,
        (__half2*)wq_hi, (__half2*)wq_lo);
    split_fp32_hi<<<(cH * cH) / 1024, 256>>>((const float4*)W_dense, (__half2*)wd_hi);

    // 1) QKV: Q/K (3-term) and V (1-term)
    tc_gemm_qk<<<dim3(2 * cNH, cM / GBM), 256, SMEM_QK>>>(
        hid_hi, hid_lo, wq_hi, wq_lo, b_qkv);
    tc_gemm_1t<2><<<dim3(cNH, cM / GBM), 256, SMEM_1T>>>(
        hid_hi, wq_hi, b_qkv, nullptr, nullptr);

    // 2) attention -> ctx fp16
    attn_mma<<<dim3(cS / ABQ, cB * cNH), 128, ATTN_SMEM>>>(alibi);

    // 3) dense (1-term) + bias + residual -> out
    tc_gemm_1t<1><<<dim3(cH / GBN, cM / GBM), 256, SMEM_1T>>>(
        cx_hi, wd_hi, b_dense, residual, out);
}

// round 13
// speedup vs baseline: 5.2823x; 1.1657x over previous
#include <cuda_runtime.h>
#include <cuda_fp16.h>
#include <math.h>
#include <cstdint>

// ---------------------------------------------------------------------------
// Problem constants
// ---------------------------------------------------------------------------
namespace {
constexpr int cB  = 2;
constexpr int cS  = 2048;
constexpr int cH  = 4096;
constexpr int cNH = 32;
constexpr int cHD = 128;
constexpr int cM  = cB * cS;      // 4096
constexpr int cQKVN = 3 * cH;     // 12288

// GEMM tiling (mma.sync path)
constexpr int GBM = 128, GBN = 128, GBK = 32;
constexpr int SKB   = 80;                 // smem row stride bytes
constexpr int TILEB = GBM * SKB;          // 10240
constexpr int STAGE3 = 3 * TILEB;         // Ah,Bh,Bl (2-term QK kernel)
constexpr int SMEM_QK = 3 * STAGE3;       // 92160 (3-stage ring)
constexpr int STAGE2 = 2 * TILEB;         // Ah,Bh (1-term kernels)
constexpr int SMEM_1T = 3 * STAGE2;       // 61440 (3-stage ring)

// Attention: q-tile 64 rows, k-tile 32 rows, double-buffered, 3 tiles/stage
constexpr int ABQ = 64;
constexpr int ROWB = 272;                 // 128 fp16 + pad = 272 bytes
constexpr int ATILE = 32 * ROWB;          // 8704
constexpr int ASTAGE = 3 * ATILE;         // KH,KL,VH = 26112
constexpr int AOFF_ALI = 2 * ASTAGE;      // 52224
constexpr int ATTN_SMEM = AOFF_ALI + 256; // 52480
}

// ---------------------------------------------------------------------------
// Scratch (__device__ globals)
// ---------------------------------------------------------------------------
__device__ __half g_qh[(size_t)cB * cNH * cS * cHD];
__device__ __half g_ql[(size_t)cB * cNH * cS * cHD];
__device__ __half g_kh[(size_t)cB * cNH * cS * cHD];
__device__ __half g_kl[(size_t)cB * cNH * cS * cHD];
__device__ __half g_vh[(size_t)cB * cNH * cS * cHD];

__device__ __half g_hid_hi[(size_t)cM * cH];
__device__ __half g_wqkv_hi[(size_t)cQKVN * cH];
__device__ __half g_wqkv_lo[(size_t)cQKVN * cH];
__device__ __half g_wd_hi[(size_t)cH * cH];
__device__ __half g_ctx_hi[(size_t)cM * cH];

// ---------------------------------------------------------------------------
// PTX helpers — non-arch-specific only (mma.sync / ldmatrix / cp.async)
// ---------------------------------------------------------------------------
__device__ __forceinline__ uint32_t smem_u32(const void* p) {
    uint32_t a;
    asm("{ .reg .u64 t; cvta.to.shared.u64 t, %1; cvt.u32.u64 %0, t; }" : "=r"(a) : "l"(p));
    return a;
}
__device__ __forceinline__ void mma_f16(float* c, const uint32_t* a, const uint32_t* b) {
    asm volatile(
        "mma.sync.aligned.m16n8k16.row.col.f32.f16.f16.f32 "
        "{%0,%1,%2,%3}, {%4,%5,%6,%7}, {%8,%9}, {%0,%1,%2,%3};"
        : "+f"(c[0]), "+f"(c[1]), "+f"(c[2]), "+f"(c[3])
        : "r"(a[0]), "r"(a[1]), "r"(a[2]), "r"(a[3]), "r"(b[0]), "r"(b[1]));
}
__device__ __forceinline__ void ldsm_x4(uint32_t* r, uint32_t addr) {
    asm volatile("ldmatrix.sync.aligned.m8n8.x4.shared.b16 {%0,%1,%2,%3}, [%4];"
                 : "=r"(r[0]), "=r"(r[1]), "=r"(r[2]), "=r"(r[3]) : "r"(addr));
}
__device__ __forceinline__ void ldsm_x4_t(uint32_t* r, uint32_t addr) {
    asm volatile("ldmatrix.sync.aligned.m8n8.x4.trans.shared.b16 {%0,%1,%2,%3}, [%4];"
                 : "=r"(r[0]), "=r"(r[1]), "=r"(r[2]), "=r"(r[3]) : "r"(addr));
}
__device__ __forceinline__ void cp_async16(uint32_t s, const void* g) {
    asm volatile("cp.async.cg.shared.global [%0], [%1], 16;" :: "r"(s), "l"(g));
}
#define CP_COMMIT() asm volatile("cp.async.commit_group;" ::: "memory")
#define CP_WAIT(n)  asm volatile("cp.async.wait_group %0;" :: "n"(n) : "memory")

__device__ __forceinline__ uint32_t pack_f16(float lo, float hi) {
    uint32_t r;
    asm("cvt.rn.f16x2.f32 %0, %1, %2;" : "=r"(r) : "f"(hi), "f"(lo));
    return r;
}
__device__ __forceinline__ float f16_round(float x) {
    return __half2float(__float2half_rn(x));
}
// exp on the FMA pipe: valid for x <= 0; flushes below -87.
__device__ __forceinline__ float fast_exp(float x) {
    x = fmaxf(x, -87.0f);
    const float L2E = 1.4426950408889634f;
    float t = fmaf(x, L2E, 12582912.0f);
    float i = t - 12582912.0f;
    float f = fmaf(x, L2E, -i);
    float p =        1.3394582e-3f;
    p = fmaf(p, f, 9.6180217e-3f);
    p = fmaf(p, f, 5.5503368e-2f);
    p = fmaf(p, f, 2.4022652e-1f);
    p = fmaf(p, f, 6.9314718e-1f);
    p = fmaf(p, f, 1.0f);
    int e = (int)i;
    return __int_as_float((uint32_t)(e + 127) << 23) * p;
}

// ---------------------------------------------------------------------------
// fp32 -> fp16 splits
// ---------------------------------------------------------------------------
__global__ __launch_bounds__(256) void split_fp32(
    const float4* __restrict__ src, __half2* __restrict__ hi, __half2* __restrict__ lo)
{
    const size_t i = (size_t)blockIdx.x * 256 + threadIdx.x;
    const float4 v = src[i];
    __half hx = __float2half_rn(v.x);
    __half hy = __float2half_rn(v.y);
    __half hz = __float2half_rn(v.z);
    __half hw = __float2half_rn(v.w);
    hi[2 * i]     = __halves2half2(hx, hy);
    hi[2 * i + 1] = __halves2half2(hz, hw);
    lo[2 * i]     = __halves2half2(__float2half_rn(v.x - __half2float(hx)),
                                   __float2half_rn(v.y - __half2float(hy)));
    lo[2 * i + 1] = __halves2half2(__float2half_rn(v.z - __half2float(hz)),
                                   __float2half_rn(v.w - __half2float(hw)));
}
__global__ __launch_bounds__(256) void split_fp32_hi(
    const float4* __restrict__ src, __half2* __restrict__ hi)
{
    const size_t i = (size_t)blockIdx.x * 256 + threadIdx.x;
    const float4 v = src[i];
    hi[2 * i]     = __halves2half2(__float2half_rn(v.x), __float2half_rn(v.y));
    hi[2 * i + 1] = __halves2half2(__float2half_rn(v.z), __float2half_rn(v.w));
}

// ---------------------------------------------------------------------------
// 2-term GEMM (fp16 split on B only): Q/K part of QKV.
// C = Ah*Bh + Ah*Bl. grid (64, 32): nh = bx>>1, t = bx&1 (0=Q, 1=K).
// 3-stage cp.async ring. Output: hi/lo fp16 scatter.
// ---------------------------------------------------------------------------
__global__ __launch_bounds__(256, 2) void tc_gemm_qk(
    const __half* __restrict__ Ahi,
    const __half* __restrict__ Bhi, const __half* __restrict__ Blo,
    const float* __restrict__ bias)
{
    extern __shared__ char smem[];
    const uint32_t sbase = smem_u32(smem);
    const int tid  = threadIdx.x;
    const int wid  = tid >> 5;
    const int lane = tid & 31;
    const int wm   = wid >> 2;
    const int wn   = wid & 3;
    const int bm   = blockIdx.y * GBM;
    const int nh   = blockIdx.x >> 1;
    const int t    = blockIdx.x & 1;
    const int obase = nh * 384 + t * 128;

    const __half* Ah = Ahi + (size_t)bm * cH;
    const __half* Bh = Bhi + (size_t)obase * cH;
    const __half* Bl = Blo + (size_t)obase * cH;

    float acc[4][4][4];
#pragma unroll
    for (int mi = 0; mi < 4; mi++)
#pragma unroll
        for (int nj = 0; nj < 4; nj++)
#pragma unroll
            for (int r = 0; r < 4; r++) acc[mi][nj][r] = 0.f;

    const int aRow = ((lane >> 3) & 1) * 8 + (lane & 7);
    const int aK   = (lane >> 4) * 8;
    const int bl15 = lane & 15;
    const int bN   = bl15 & 7;
    const int bK   = (bl15 >> 3) * 8;
    // merged hi/lo B: lanes 0-15 -> Bh tile, lanes 16-31 -> Bl tile
    const uint32_t bTile = (lane >= 16) ? (uint32_t)(2 * TILEB) : (uint32_t)(1 * TILEB);

    auto load_chunk = [&](int stage, int k0) {
        const uint32_t sg = sbase + stage * STAGE3;
#pragma unroll
        for (int it = 0; it < 2; ++it) {
            const int c   = tid + it * 256;
            const int row = c >> 2;
            const int kc  = c & 3;
            const uint32_t so = (uint32_t)(row * SKB + kc * 16);
            const size_t  go  = (size_t)row * cH + k0 + kc * 8;
            cp_async16(sg + 0 * TILEB + so, Ah + go);
            cp_async16(sg + 1 * TILEB + so, Bh + go);
            cp_async16(sg + 2 * TILEB + so, Bl + go);
        }
    };

    constexpr int NCH = cH / GBK;   // 128
    load_chunk(0, 0);
    CP_COMMIT();
    load_chunk(1, GBK);
    CP_COMMIT();

    int cstage = 0;
    for (int ch = 0; ch < NCH; ++ch) {
        if (ch + 1 < NCH) { CP_WAIT(1); } else { CP_WAIT(0); }
        __syncthreads();
        if (ch + 2 < NCH) {
            int lstage = cstage - 1; if (lstage < 0) lstage = 2;   // (cstage+2)%3
            load_chunk(lstage, (ch + 2) * GBK);
            CP_COMMIT();
        }
        const uint32_t st = sbase + cstage * STAGE3;
#pragma unroll
        for (int ks = 0; ks < 2; ++ks) {
            uint32_t ah[4][4];
#pragma unroll
            for (int mi = 0; mi < 4; ++mi) {
                const uint32_t ao =
                    (uint32_t)((wm * 64 + mi * 16 + aRow) * SKB + (ks * 16 + aK) * 2);
                ldsm_x4(ah[mi], st + ao);
            }
#pragma unroll
            for (int nj = 0; nj < 4; ++nj) {
                uint32_t bb[4];     // [0..1]=Bh frag, [2..3]=Bl frag (lane-merged)
                const uint32_t bo =
                    (uint32_t)((wn * 32 + nj * 8 + bN) * SKB + (ks * 16 + bK) * 2);
                ldsm_x4(bb, st + bTile + bo);
#pragma unroll
                for (int mi = 0; mi < 4; ++mi) {
                    mma_f16(acc[mi][nj], ah[mi], bb);
                    mma_f16(acc[mi][nj], ah[mi], bb + 2);
                }
            }
        }
        cstage = (cstage == 2) ? 0 : cstage + 1;
    }

    const int l4 = lane >> 2;
    const int l2 = (lane & 3) * 2;
    __half* dh = t ? g_kh : g_qh;
    __half* dl = t ? g_kl : g_ql;
#pragma unroll
    for (int mi = 0; mi < 4; ++mi) {
#pragma unroll
        for (int nj = 0; nj < 4; ++nj) {
            const int colT = wn * 32 + nj * 8 + l2;
            const float2 bia = *(const float2*)&bias[obase + colT];
#pragma unroll
            for (int half = 0; half < 2; ++half) {
                const int m = bm + wm * 64 + mi * 16 + l4 + half * 8;
                const float vx = acc[mi][nj][half * 2 + 0] + bia.x;
                const float vy = acc[mi][nj][half * 2 + 1] + bia.y;
                const int b = m / cS, s = m % cS;
                const size_t idx = ((size_t)(b * cNH + nh) * cS + s) * cHD + colT;
                *(uint32_t*)&dh[idx] = pack_f16(vx, vy);
                *(uint32_t*)&dl[idx] = pack_f16(vx - f16_round(vx), vy - f16_round(vy));
            }
        }
    }
}

// ---------------------------------------------------------------------------
// 1-term GEMM (plain fp16): MODE 2 = V part of QKV (scatter vh), MODE 1 = dense.
// 3-stage cp.async ring.
// ---------------------------------------------------------------------------
template <int MODE>
__global__ __launch_bounds__(256, 2) void tc_gemm_1t(
    const __half* __restrict__ Ahi, const __half* __restrict__ Bhi,
    const float* __restrict__ bias,
    const float* __restrict__ residual,
    float* __restrict__ out)
{
    extern __shared__ char smem[];
    const uint32_t sbase = smem_u32(smem);
    const int tid  = threadIdx.x;
    const int wid  = tid >> 5;
    const int lane = tid & 31;
    const int wm   = wid >> 2;
    const int wn   = wid & 3;
    const int bm   = blockIdx.y * GBM;
    const int obase = (MODE == 2) ? ((int)blockIdx.x * 384 + 256) : ((int)blockIdx.x * 128);

    const __half* Ah = Ahi + (size_t)bm * cH;
    const __half* Bh = Bhi + (size_t)obase * cH;

    float acc[4][4][4];
#pragma unroll
    for (int mi = 0; mi < 4; mi++)
#pragma unroll
        for (int nj = 0; nj < 4; nj++)
#pragma unroll
            for (int r = 0; r < 4; r++) acc[mi][nj][r] = 0.f;

    const int aRow = ((lane >> 3) & 1) * 8 + (lane & 7);
    const int aK   = (lane >> 4) * 8;
    const int bRow = ((lane >> 4) << 3) + (lane & 7);   // n-row within 16
    const int bK   = ((lane >> 3) & 1) * 8;

    auto load_chunk = [&](int stage, int k0) {
        const uint32_t sg = sbase + stage * STAGE2;
#pragma unroll
        for (int it = 0; it < 2; ++it) {
            const int c   = tid + it * 256;
            const int row = c >> 2;
            const int kc  = c & 3;
            const uint32_t so = (uint32_t)(row * SKB + kc * 16);
            const size_t  go  = (size_t)row * cH + k0 + kc * 8;
            cp_async16(sg + 0 * TILEB + so, Ah + go);
            cp_async16(sg + 1 * TILEB + so, Bh + go);
        }
    };

    constexpr int NCH = cH / GBK;
    load_chunk(0, 0);
    CP_COMMIT();
    load_chunk(1, GBK);
    CP_COMMIT();

    int cstage = 0;
    for (int ch = 0; ch < NCH; ++ch) {
        if (ch + 1 < NCH) { CP_WAIT(1); } else { CP_WAIT(0); }
        __syncthreads();
        if (ch + 2 < NCH) {
            int lstage = cstage - 1; if (lstage < 0) lstage = 2;
            load_chunk(lstage, (ch + 2) * GBK);
            CP_COMMIT();
        }
        const uint32_t st = sbase + cstage * STAGE2;
#pragma unroll
        for (int ks = 0; ks < 2; ++ks) {
            uint32_t ah[4][4];
#pragma unroll
            for (int mi = 0; mi < 4; ++mi) {
                const uint32_t ao =
                    (uint32_t)((wm * 64 + mi * 16 + aRow) * SKB + (ks * 16 + aK) * 2);
                ldsm_x4(ah[mi], st + ao);
            }
#pragma unroll
            for (int nj2 = 0; nj2 < 2; ++nj2) {
                uint32_t bb[4];
                const uint32_t bo =
                    (uint32_t)((wn * 32 + nj2 * 16 + bRow) * SKB + (ks * 16 + bK) * 2);
                ldsm_x4(bb, st + TILEB + bo);
#pragma unroll
                for (int mi = 0; mi < 4; ++mi) {
                    mma_f16(acc[mi][2 * nj2],     ah[mi], bb);
                    mma_f16(acc[mi][2 * nj2 + 1], ah[mi], bb + 2);
                }
            }
        }
        cstage = (cstage == 2) ? 0 : cstage + 1;
    }

    const int l4 = lane >> 2;
    const int l2 = (lane & 3) * 2;
#pragma unroll
    for (int mi = 0; mi < 4; ++mi) {
#pragma unroll
        for (int nj = 0; nj < 4; ++nj) {
            const int colT = wn * 32 + nj * 8 + l2;
            const int o    = obase + colT;
            const float2 bia = *(const float2*)&bias[o];
#pragma unroll
            for (int half = 0; half < 2; ++half) {
                const int m = bm + wm * 64 + mi * 16 + l4 + half * 8;
                const float vx = acc[mi][nj][half * 2 + 0] + bia.x;
                const float vy = acc[mi][nj][half * 2 + 1] + bia.y;
                if (MODE == 2) {
                    const int b = m / cS, s = m % cS;
                    const size_t idx =
                        ((size_t)(b * cNH + blockIdx.x) * cS + s) * cHD + colT;
                    *(uint32_t*)&g_vh[idx] = pack_f16(vx, vy);
                } else {
                    const size_t idx = (size_t)m * cH + o;
                    const float2 res = *(const float2*)&residual[idx];
                    float2 v; v.x = vx + res.x; v.y = vy + res.y;
                    *(float2*)&out[idx] = v;
                }
            }
        }
    }
}

// ---------------------------------------------------------------------------
// Attention: 64 q-rows/CTA, 4 warps; 32-row K/V tiles double-buffered.
// QK = 3-term fp16 (protected path); PV = 1-term fp16.
// ---------------------------------------------------------------------------
__global__ __launch_bounds__(128) void attn_mma(const float* __restrict__ alibi)
{
    extern __shared__ char sm[];
    const uint32_t sb = smem_u32(sm);
    const int tid  = threadIdx.x;
    const int lane = tid & 31;
    const int w    = tid >> 5;
    const int qi   = (cS / ABQ - 1) - blockIdx.x;   // big tiles first
    const int bh   = blockIdx.y;
    const int b    = bh >> 5;
    const int nh   = bh & 31;
    const size_t hb = (size_t)bh * cS * cHD;
    const float inv_norm = 0.08838834764831845f;

    const int g    = lane >> 2;
    const int tig  = lane & 3;
    const int aRow = ((lane >> 3) & 1) * 8 + (lane & 7);
    const int aK   = (lane >> 4) * 8;
    const int bl15 = lane & 15;
    const int bN   = bl15 & 7;
    const int bK   = (bl15 >> 3) * 8;
    const uint32_t kSel = (lane >= 16) ? (uint32_t)ATILE : 0u;   // KL vs KH
    const int vRow = (lane & 7) + (((lane >> 3) & 1) << 3);
    const int vSel = lane >> 4;

    // ---- stage Q (64 rows): qh @ stage0, ql @ stage1
#pragma unroll
    for (int i = 0; i < 8; i++) {
        const int id = tid + i * 128;
        const int r = id >> 4, c = id & 15;
        const size_t go = hb + (size_t)(qi * ABQ + r) * cHD + c * 8;
        const uint32_t so = (uint32_t)(r * ROWB + c * 16);
        cp_async16(sb + so, g_qh + go);
        cp_async16(sb + ASTAGE + so, g_ql + go);
    }
    CP_COMMIT(); CP_WAIT(0);
    __syncthreads();

    uint32_t qh[8][4], ql[8][4];
#pragma unroll
    for (int ks = 0; ks < 8; ks++) {
        const uint32_t ao = (uint32_t)((w * 16 + aRow) * ROWB + (ks * 16 + aK) * 2);
        ldsm_x4(qh[ks], sb + ao);
        ldsm_x4(ql[ks], sb + ASTAGE + ao);
    }
    __syncthreads();

    float ctx[16][4];
#pragma unroll
    for (int t = 0; t < 16; t++)
#pragma unroll
        for (int r = 0; r < 4; r++) ctx[t][r] = 0.f;
    float m1 = -INFINITY, m2 = -INFINITY, l1 = 0.f, l2 = 0.f;
    const int row1 = qi * ABQ + w * 16 + g;
    const int row2 = row1 + 8;

    auto load_kv = [&](int stage, int kt) {
        const uint32_t stb = sb + stage * ASTAGE;
#pragma unroll
        for (int i = 0; i < 4; i++) {
            const int id = tid + i * 128;
            const int r = id >> 4, c = id & 15;
            const size_t go = hb + (size_t)(kt * 32 + r) * cHD + c * 8;
            const uint32_t so = (uint32_t)(r * ROWB + c * 16);
            cp_async16(stb + 0 * ATILE + so, g_kh + go);
            cp_async16(stb + 1 * ATILE + so, g_kl + go);
            cp_async16(stb + 2 * ATILE + so, g_vh + go);
        }
        if (tid < 32)
            ((float*)(sm + AOFF_ALI + stage * 128))[tid] =
                alibi[(size_t)bh * cS + kt * 32 + tid];
    };

    const int nkt = 2 * (qi + 1);
    load_kv(0, 0);
    CP_COMMIT();

    for (int kt = 0; kt < nkt; kt++) {
        CP_WAIT(0);
        __syncthreads();
        if (kt + 1 < nkt) { load_kv((kt + 1) & 1, kt + 1); CP_COMMIT(); }
        const uint32_t stb = sb + (kt & 1) * ASTAGE;
        const float* als = (const float*)(sm + AOFF_ALI + (kt & 1) * 128);

        // ---- S = Q K^T (3-term)
        float sacc[4][4];
#pragma unroll
        for (int j = 0; j < 4; j++)
#pragma unroll
            for (int r = 0; r < 4; r++) sacc[j][r] = 0.f;

#pragma unroll
        for (int j = 0; j < 4; j++) {
#pragma unroll
            for (int ks = 0; ks < 8; ks++) {
                uint32_t kb[4];   // [0..1]=Kh, [2..3]=Kl (lane-merged)
                const uint32_t bo =
                    (uint32_t)((j * 8 + bN) * ROWB + (ks * 16 + bK) * 2);
                ldsm_x4(kb, stb + kSel + bo);
                mma_f16(sacc[j], qh[ks], kb);
                mma_f16(sacc[j], qh[ks], kb + 2);
                mma_f16(sacc[j], ql[ks], kb);
            }
        }

        // ---- scale + alibi + causal mask (only last two tiles can mask)
        const bool maskt = (kt >= 2 * qi);
#pragma unroll
        for (int j = 0; j < 4; j++) {
            const int c0 = j * 8 + tig * 2;
            const float a0 = als[c0], a1 = als[c0 + 1];
            sacc[j][0] = fmaf(sacc[j][0], inv_norm, a0);
            sacc[j][1] = fmaf(sacc[j][1], inv_norm, a1);
            sacc[j][2] = fmaf(sacc[j][2], inv_norm, a0);
            sacc[j][3] = fmaf(sacc[j][3], inv_norm, a1);
            if (maskt) {
                const int cg = kt * 32 + c0;
                if (cg     > row1) sacc[j][0] = -100000.0f;
                if (cg + 1 > row1) sacc[j][1] = -100000.0f;
                if (cg     > row2) sacc[j][2] = -100000.0f;
                if (cg + 1 > row2) sacc[j][3] = -100000.0f;
            }
        }

        // ---- online softmax
        float mx1 = -INFINITY, mx2 = -INFINITY;
#pragma unroll
        for (int j = 0; j < 4; j++) {
            mx1 = fmaxf(mx1, fmaxf(sacc[j][0], sacc[j][1]));
            mx2 = fmaxf(mx2, fmaxf(sacc[j][2], sacc[j][3]));
        }
        mx1 = fmaxf(mx1, __shfl_xor_sync(0xffffffffu, mx1, 1));
        mx1 = fmaxf(mx1, __shfl_xor_sync(0xffffffffu, mx1, 2));
        mx2 = fmaxf(mx2, __shfl_xor_sync(0xffffffffu, mx2, 1));
        mx2 = fmaxf(mx2, __shfl_xor_sync(0xffffffffu, mx2, 2));

        const float mn1 = fmaxf(m1, mx1), mn2 = fmaxf(m2, mx2);
        const float sc1 = fast_exp(m1 - mn1), sc2 = fast_exp(m2 - mn2);
        float ls1 = 0.f, ls2 = 0.f;
#pragma unroll
        for (int j = 0; j < 4; j++) {
            sacc[j][0] = fast_exp(sacc[j][0] - mn1);
            sacc[j][1] = fast_exp(sacc[j][1] - mn1);
            sacc[j][2] = fast_exp(sacc[j][2] - mn2);
            sacc[j][3] = fast_exp(sacc[j][3] - mn2);
            ls1 += sacc[j][0] + sacc[j][1];
            ls2 += sacc[j][2] + sacc[j][3];
        }
        ls1 += __shfl_xor_sync(0xffffffffu, ls1, 1);
        ls1 += __shfl_xor_sync(0xffffffffu, ls1, 2);
        ls2 += __shfl_xor_sync(0xffffffffu, ls2, 1);
        ls2 += __shfl_xor_sync(0xffffffffu, ls2, 2);
        l1 = l1 * sc1 + ls1;  l2 = l2 * sc2 + ls2;
        m1 = mn1;             m2 = mn2;
#pragma unroll
        for (int t = 0; t < 16; t++) {
            ctx[t][0] *= sc1; ctx[t][1] *= sc1;
            ctx[t][2] *= sc2; ctx[t][3] *= sc2;
        }

        // ---- ctx += P V (1-term: Ph x Vh)
#pragma unroll
        for (int ks2 = 0; ks2 < 2; ks2++) {
            uint32_t pah[4];
            pah[0] = pack_f16(sacc[2 * ks2][0],     sacc[2 * ks2][1]);
            pah[1] = pack_f16(sacc[2 * ks2][2],     sacc[2 * ks2][3]);
            pah[2] = pack_f16(sacc[2 * ks2 + 1][0], sacc[2 * ks2 + 1][1]);
            pah[3] = pack_f16(sacc[2 * ks2 + 1][2], sacc[2 * ks2 + 1][3]);
#pragma unroll
            for (int p2 = 0; p2 < 8; p2++) {
                uint32_t vbh[4];
                const uint32_t vo =
                    (uint32_t)((ks2 * 16 + vRow) * ROWB + (p2 * 16 + vSel * 8) * 2);
                ldsm_x4_t(vbh, stb + 2 * ATILE + vo);
                mma_f16(ctx[2 * p2],     pah, vbh);
                mma_f16(ctx[2 * p2 + 1], pah, vbh + 2);
            }
        }
    }

    // ---- epilogue: normalize, fp16 ctx (hi only)
    const float inv1 = 1.0f / l1, inv2 = 1.0f / l2;
    const size_t o1 = (size_t)(b * cS + row1) * cH + nh * cHD;
    const size_t o2 = (size_t)(b * cS + row2) * cH + nh * cHD;
#pragma unroll
    for (int t = 0; t < 16; t++) {
        const int d = t * 8 + tig * 2;
        *(uint32_t*)&g_ctx_hi[o1 + d] = pack_f16(ctx[t][0] * inv1, ctx[t][1] * inv1);
        *(uint32_t*)&g_ctx_hi[o2 + d] = pack_f16(ctx[t][2] * inv2, ctx[t][3] * inv2);
    }
}

// ---------------------------------------------------------------------------
// Launch
// ---------------------------------------------------------------------------
extern "C" void kernel_launch(void* const* d_in, const int* in_sizes, int n_in,
                              void* d_out, int out_size)
{
    (void)in_sizes; (void)n_in; (void)out_size;
    const float* hidden   = (const float*)d_in[0];
    const float* residual = (const float*)d_in[1];
    const float* alibi    = (const float*)d_in[2];
    const float* W_qkv    = (const float*)d_in[4];
    const float* b_qkv    = (const float*)d_in[5];
    const float* W_dense  = (const float*)d_in[6];
    const float* b_dense  = (const float*)d_in[7];
    float* out = (float*)d_out;

    cudaFuncSetAttribute(tc_gemm_qk,    cudaFuncAttributeMaxDynamicSharedMemorySize, SMEM_QK);
    cudaFuncSetAttribute(tc_gemm_1t<2>, cudaFuncAttributeMaxDynamicSharedMemorySize, SMEM_1T);
    cudaFuncSetAttribute(tc_gemm_1t<1>, cudaFuncAttributeMaxDynamicSharedMemorySize, SMEM_1T);
    cudaFuncSetAttribute(attn_mma,      cudaFuncAttributeMaxDynamicSharedMemorySize, ATTN_SMEM);

    __half *hid_hi, *wq_hi, *wq_lo, *wd_hi, *cx_hi;
    cudaGetSymbolAddress((void**)&hid_hi, g_hid_hi);
    cudaGetSymbolAddress((void**)&wq_hi,  g_wqkv_hi);
    cudaGetSymbolAddress((void**)&wq_lo,  g_wqkv_lo);
    cudaGetSymbolAddress((void**)&wd_hi,  g_wd_hi);
    cudaGetSymbolAddress((void**)&cx_hi,  g_ctx_hi);

    // 0) fp32 -> fp16 splits (hidden hi-only now: its residual is dropped
    //    everywhere by the 2-term scheme)
    split_fp32_hi<<<(cM * cH) / 1024, 256>>>((const float4*)hidden, (__half2*)hid_hi);
    split_fp32<<<(cQKVN * cH) / 1024, 256>>>((const float4*)W_qkv,
        (__half2*)wq_hi, (__half2*)wq_lo);
    split_fp32_hi<<<(cH * cH) / 1024, 256>>>((const float4*)W_dense, (__half2*)wd_hi);

    // 1) QKV: Q/K (2-term) and V (1-term)
    tc_gemm_qk<<<dim3(2 * cNH, cM / GBM), 256, SMEM_QK>>>(
        hid_hi, wq_hi, wq_lo, b_qkv);
    tc_gemm_1t<2><<<dim3(cNH, cM / GBM), 256, SMEM_1T>>>(
        hid_hi, wq_hi, b_qkv, nullptr, nullptr);

    // 2) attention -> ctx fp16
    attn_mma<<<dim3(cS / ABQ, cB * cNH), 128, ATTN_SMEM>>>(alibi);

    // 3) dense (1-term) + bias + residual -> out
    tc_gemm_1t<1><<<dim3(cH / GBN, cM / GBM), 256, SMEM_1T>>>(
        cx_hi, wd_hi, b_dense, residual, out);
}

// round 15
// speedup vs baseline: 7.8157x; 1.4796x over previous
#include <cuda_runtime.h>
#include <cuda_fp16.h>
#include <math.h>
#include <cstdint>

// ---------------------------------------------------------------------------
// Problem constants
// ---------------------------------------------------------------------------
namespace {
constexpr int cB  = 2;
constexpr int cS  = 2048;
constexpr int cH  = 4096;
constexpr int cNH = 32;
constexpr int cHD = 128;
constexpr int cM  = cB * cS;      // 4096
constexpr int cQKVN = 3 * cH;     // 12288

// GEMM tiling (mma.sync path)
constexpr int GBM = 128, GBN = 128, GBK = 32;
constexpr int SKB   = 80;                 // smem row stride bytes
constexpr int TILEB = GBM * SKB;          // 10240
constexpr int STAGE2 = 2 * TILEB;         // Ah,Bh (1-term kernels)
constexpr int SMEM_1T = 3 * STAGE2;       // 61440 (3-stage ring)

// Attention: q-tile 64 rows, k-tile 32 rows, double-buffered, 2 tiles/stage
constexpr int ABQ = 64;
constexpr int ROWB = 272;                 // 128 fp16 + pad = 272 bytes
constexpr int ATILE = 32 * ROWB;          // 8704
constexpr int ASTAGE = 2 * ATILE;         // KH,VH = 17408
constexpr int AOFF_ALI = 2 * ASTAGE;      // 34816
constexpr int ATTN_SMEM = AOFF_ALI + 256; // 35072
}

// ---------------------------------------------------------------------------
// Scratch (__device__ globals)
// ---------------------------------------------------------------------------
__device__ __half g_qh[(size_t)cB * cNH * cS * cHD];
__device__ __half g_kh[(size_t)cB * cNH * cS * cHD];
__device__ __half g_vh[(size_t)cB * cNH * cS * cHD];

__device__ __half g_hid_hi[(size_t)cM * cH];
__device__ __half g_wqkv_hi[(size_t)cQKVN * cH];
__device__ __half g_wd_hi[(size_t)cH * cH];
__device__ __half g_ctx_hi[(size_t)cM * cH];

// ---------------------------------------------------------------------------
// PTX helpers — non-arch-specific only (mma.sync / ldmatrix / cp.async)
// ---------------------------------------------------------------------------
__device__ __forceinline__ uint32_t smem_u32(const void* p) {
    uint32_t a;
    asm("{ .reg .u64 t; cvta.to.shared.u64 t, %1; cvt.u32.u64 %0, t; }" : "=r"(a) : "l"(p));
    return a;
}
__device__ __forceinline__ void mma_f16(float* c, const uint32_t* a, const uint32_t* b) {
    asm volatile(
        "mma.sync.aligned.m16n8k16.row.col.f32.f16.f16.f32 "
        "{%0,%1,%2,%3}, {%4,%5,%6,%7}, {%8,%9}, {%0,%1,%2,%3};"
        : "+f"(c[0]), "+f"(c[1]), "+f"(c[2]), "+f"(c[3])
        : "r"(a[0]), "r"(a[1]), "r"(a[2]), "r"(a[3]), "r"(b[0]), "r"(b[1]));
}
__device__ __forceinline__ void ldsm_x4(uint32_t* r, uint32_t addr) {
    asm volatile("ldmatrix.sync.aligned.m8n8.x4.shared.b16 {%0,%1,%2,%3}, [%4];"
                 : "=r"(r[0]), "=r"(r[1]), "=r"(r[2]), "=r"(r[3]) : "r"(addr));
}
__device__ __forceinline__ void ldsm_x4_t(uint32_t* r, uint32_t addr) {
    asm volatile("ldmatrix.sync.aligned.m8n8.x4.trans.shared.b16 {%0,%1,%2,%3}, [%4];"
                 : "=r"(r[0]), "=r"(r[1]), "=r"(r[2]), "=r"(r[3]) : "r"(addr));
}
__device__ __forceinline__ void cp_async16(uint32_t s, const void* g) {
    asm volatile("cp.async.cg.shared.global [%0], [%1], 16;" :: "r"(s), "l"(g));
}
#define CP_COMMIT() asm volatile("cp.async.commit_group;" ::: "memory")
#define CP_WAIT(n)  asm volatile("cp.async.wait_group %0;" :: "n"(n) : "memory")

__device__ __forceinline__ uint32_t pack_f16(float lo, float hi) {
    uint32_t r;
    asm("cvt.rn.f16x2.f32 %0, %1, %2;" : "=r"(r) : "f"(hi), "f"(lo));
    return r;
}
// exp on the FMA pipe: valid for x <= 0; flushes below -87.
__device__ __forceinline__ float fast_exp(float x) {
    x = fmaxf(x, -87.0f);
    const float L2E = 1.4426950408889634f;
    float t = fmaf(x, L2E, 12582912.0f);
    float i = t - 12582912.0f;
    float f = fmaf(x, L2E, -i);
    float p =        1.3394582e-3f;
    p = fmaf(p, f, 9.6180217e-3f);
    p = fmaf(p, f, 5.5503368e-2f);
    p = fmaf(p, f, 2.4022652e-1f);
    p = fmaf(p, f, 6.9314718e-1f);
    p = fmaf(p, f, 1.0f);
    int e = (int)i;
    return __int_as_float((uint32_t)(e + 127) << 23) * p;
}

// ---------------------------------------------------------------------------
// fp32 -> fp16 (hi only)
// ---------------------------------------------------------------------------
__global__ __launch_bounds__(256) void split_fp32_hi(
    const float4* __restrict__ src, __half2* __restrict__ hi)
{
    const size_t i = (size_t)blockIdx.x * 256 + threadIdx.x;
    const float4 v = src[i];
    hi[2 * i]     = __halves2half2(__float2half_rn(v.x), __float2half_rn(v.y));
    hi[2 * i + 1] = __halves2half2(__float2half_rn(v.z), __float2half_rn(v.w));
}

// ---------------------------------------------------------------------------
// 1-term fp16 GEMM, 3-stage cp.async ring.
// MODE 0: QKV -> scatter fp16 into g_qh/g_kh/g_vh (+bias); grid (96, 32).
// MODE 1: dense -> out = acc + bias + residual (fp32); grid (32, 32).
// ---------------------------------------------------------------------------
template <int MODE>
__global__ __launch_bounds__(256, 2) void tc_gemm_1t(
    const __half* __restrict__ Ahi, const __half* __restrict__ Bhi,
    const float* __restrict__ bias,
    const float* __restrict__ residual,
    float* __restrict__ out)
{
    extern __shared__ char smem[];
    const uint32_t sbase = smem_u32(smem);
    const int tid  = threadIdx.x;
    const int wid  = tid >> 5;
    const int lane = tid & 31;
    const int wm   = wid >> 2;
    const int wn   = wid & 3;
    const int bm   = blockIdx.y * GBM;
    const int obase = (int)blockIdx.x * 128;

    const __half* Ah = Ahi + (size_t)bm * cH;
    const __half* Bh = Bhi + (size_t)obase * cH;

    float acc[4][4][4];
#pragma unroll
    for (int mi = 0; mi < 4; mi++)
#pragma unroll
        for (int nj = 0; nj < 4; nj++)
#pragma unroll
            for (int r = 0; r < 4; r++) acc[mi][nj][r] = 0.f;

    const int aRow = ((lane >> 3) & 1) * 8 + (lane & 7);
    const int aK   = (lane >> 4) * 8;
    const int bRow = ((lane >> 4) << 3) + (lane & 7);   // n-row within 16
    const int bK   = ((lane >> 3) & 1) * 8;

    auto load_chunk = [&](int stage, int k0) {
        const uint32_t sg = sbase + stage * STAGE2;
#pragma unroll
        for (int it = 0; it < 2; ++it) {
            const int c   = tid + it * 256;
            const int row = c >> 2;
            const int kc  = c & 3;
            const uint32_t so = (uint32_t)(row * SKB + kc * 16);
            const size_t  go  = (size_t)row * cH + k0 + kc * 8;
            cp_async16(sg + 0 * TILEB + so, Ah + go);
            cp_async16(sg + 1 * TILEB + so, Bh + go);
        }
    };

    constexpr int NCH = cH / GBK;
    load_chunk(0, 0);
    CP_COMMIT();
    load_chunk(1, GBK);
    CP_COMMIT();

    int cstage = 0;
    for (int ch = 0; ch < NCH; ++ch) {
        if (ch + 1 < NCH) { CP_WAIT(1); } else { CP_WAIT(0); }
        __syncthreads();
        if (ch + 2 < NCH) {
            int lstage = cstage - 1; if (lstage < 0) lstage = 2;
            load_chunk(lstage, (ch + 2) * GBK);
            CP_COMMIT();
        }
        const uint32_t st = sbase + cstage * STAGE2;
#pragma unroll
        for (int ks = 0; ks < 2; ++ks) {
            uint32_t ah[4][4];
#pragma unroll
            for (int mi = 0; mi < 4; ++mi) {
                const uint32_t ao =
                    (uint32_t)((wm * 64 + mi * 16 + aRow) * SKB + (ks * 16 + aK) * 2);
                ldsm_x4(ah[mi], st + ao);
            }
#pragma unroll
            for (int nj2 = 0; nj2 < 2; ++nj2) {
                uint32_t bb[4];
                const uint32_t bo =
                    (uint32_t)((wn * 32 + nj2 * 16 + bRow) * SKB + (ks * 16 + bK) * 2);
                ldsm_x4(bb, st + TILEB + bo);
#pragma unroll
                for (int mi = 0; mi < 4; ++mi) {
                    mma_f16(acc[mi][2 * nj2],     ah[mi], bb);
                    mma_f16(acc[mi][2 * nj2 + 1], ah[mi], bb + 2);
                }
            }
        }
        cstage = (cstage == 2) ? 0 : cstage + 1;
    }

    const int l4 = lane >> 2;
    const int l2 = (lane & 3) * 2;
#pragma unroll
    for (int mi = 0; mi < 4; ++mi) {
#pragma unroll
        for (int nj = 0; nj < 4; ++nj) {
            const int colT = wn * 32 + nj * 8 + l2;
            const int o    = obase + colT;
            const float2 bia = *(const float2*)&bias[o];
#pragma unroll
            for (int half = 0; half < 2; ++half) {
                const int m = bm + wm * 64 + mi * 16 + l4 + half * 8;
                const float vx = acc[mi][nj][half * 2 + 0] + bia.x;
                const float vy = acc[mi][nj][half * 2 + 1] + bia.y;
                if (MODE == 0) {
                    const int nh = blockIdx.x / 3;
                    const int t  = blockIdx.x % 3;
                    __half* dst = (t == 0) ? g_qh : (t == 1) ? g_kh : g_vh;
                    const int b = m / cS, s = m % cS;
                    const size_t idx =
                        ((size_t)(b * cNH + nh) * cS + s) * cHD + colT;
                    *(uint32_t*)&dst[idx] = pack_f16(vx, vy);
                } else {
                    const size_t idx = (size_t)m * cH + o;
                    const float2 res = *(const float2*)&residual[idx];
                    float2 v; v.x = vx + res.x; v.y = vy + res.y;
                    *(float2*)&out[idx] = v;
                }
            }
        }
    }
}

// ---------------------------------------------------------------------------
// Attention: 64 q-rows/CTA, 4 warps; 32-row K/V tiles double-buffered.
// QK and PV both 1-term fp16 (q,k,v are fp16-exact inputs to the MMA).
// ---------------------------------------------------------------------------
__global__ __launch_bounds__(128) void attn_mma(const float* __restrict__ alibi)
{
    extern __shared__ char sm[];
    const uint32_t sb = smem_u32(sm);
    const int tid  = threadIdx.x;
    const int lane = tid & 31;
    const int w    = tid >> 5;
    const int qi   = (cS / ABQ - 1) - blockIdx.x;   // big tiles first
    const int bh   = blockIdx.y;
    const int b    = bh >> 5;
    const int nh   = bh & 31;
    const size_t hb = (size_t)bh * cS * cHD;
    const float inv_norm = 0.08838834764831845f;

    const int g    = lane >> 2;
    const int tig  = lane & 3;
    const int aRow = ((lane >> 3) & 1) * 8 + (lane & 7);
    const int aK   = (lane >> 4) * 8;
    const int bRow = ((lane >> 4) << 3) + (lane & 7);   // n-row within 16
    const int bK   = ((lane >> 3) & 1) * 8;
    const int vRow = (lane & 7) + (((lane >> 3) & 1) << 3);
    const int vSel = lane >> 4;

    // ---- stage Q (64 rows) into [0, 64*ROWB) = both stage areas (pre-loop)
#pragma unroll
    for (int i = 0; i < 8; i++) {
        const int id = tid + i * 128;
        const int r = id >> 4, c = id & 15;
        const size_t go = hb + (size_t)(qi * ABQ + r) * cHD + c * 8;
        cp_async16(sb + (uint32_t)(r * ROWB + c * 16), g_qh + go);
    }
    CP_COMMIT(); CP_WAIT(0);
    __syncthreads();

    uint32_t qh[8][4];
#pragma unroll
    for (int ks = 0; ks < 8; ks++) {
        const uint32_t ao = (uint32_t)((w * 16 + aRow) * ROWB + (ks * 16 + aK) * 2);
        ldsm_x4(qh[ks], sb + ao);
    }
    __syncthreads();

    float ctx[16][4];
#pragma unroll
    for (int t = 0; t < 16; t++)
#pragma unroll
        for (int r = 0; r < 4; r++) ctx[t][r] = 0.f;
    float m1 = -INFINITY, m2 = -INFINITY, l1 = 0.f, l2 = 0.f;
    const int row1 = qi * ABQ + w * 16 + g;
    const int row2 = row1 + 8;

    auto load_kv = [&](int stage, int kt) {
        const uint32_t stb = sb + stage * ASTAGE;
#pragma unroll
        for (int i = 0; i < 4; i++) {
            const int id = tid + i * 128;
            const int r = id >> 4, c = id & 15;
            const size_t go = hb + (size_t)(kt * 32 + r) * cHD + c * 8;
            const uint32_t so = (uint32_t)(r * ROWB + c * 16);
            cp_async16(stb + 0 * ATILE + so, g_kh + go);
            cp_async16(stb + 1 * ATILE + so, g_vh + go);
        }
        if (tid < 32)
            ((float*)(sm + AOFF_ALI + stage * 128))[tid] =
                alibi[(size_t)bh * cS + kt * 32 + tid];
    };

    const int nkt = 2 * (qi + 1);
    load_kv(0, 0);
    CP_COMMIT();

    for (int kt = 0; kt < nkt; kt++) {
        CP_WAIT(0);
        __syncthreads();
        if (kt + 1 < nkt) { load_kv((kt + 1) & 1, kt + 1); CP_COMMIT(); }
        const uint32_t stb = sb + (kt & 1) * ASTAGE;
        const float* als = (const float*)(sm + AOFF_ALI + (kt & 1) * 128);

        // ---- S = Q K^T (1-term)
        float sacc[4][4];
#pragma unroll
        for (int j = 0; j < 4; j++)
#pragma unroll
            for (int r = 0; r < 4; r++) sacc[j][r] = 0.f;

#pragma unroll
        for (int nj2 = 0; nj2 < 2; ++nj2) {
#pragma unroll
            for (int ks = 0; ks < 8; ks++) {
                uint32_t kb[4];
                const uint32_t bo =
                    (uint32_t)((nj2 * 16 + bRow) * ROWB + (ks * 16 + bK) * 2);
                ldsm_x4(kb, stb + bo);
                mma_f16(sacc[2 * nj2],     qh[ks], kb);
                mma_f16(sacc[2 * nj2 + 1], qh[ks], kb + 2);
            }
        }

        // ---- scale + alibi + causal mask (only last two tiles can mask)
        const bool maskt = (kt >= 2 * qi);
#pragma unroll
        for (int j = 0; j < 4; j++) {
            const int c0 = j * 8 + tig * 2;
            const float a0 = als[c0], a1 = als[c0 + 1];
            sacc[j][0] = fmaf(sacc[j][0], inv_norm, a0);
            sacc[j][1] = fmaf(sacc[j][1], inv_norm, a1);
            sacc[j][2] = fmaf(sacc[j][2], inv_norm, a0);
            sacc[j][3] = fmaf(sacc[j][3], inv_norm, a1);
            if (maskt) {
                const int cg = kt * 32 + c0;
                if (cg     > row1) sacc[j][0] = -100000.0f;
                if (cg + 1 > row1) sacc[j][1] = -100000.0f;
                if (cg     > row2) sacc[j][2] = -100000.0f;
                if (cg + 1 > row2) sacc[j][3] = -100000.0f;
            }
        }

        // ---- online softmax
        float mx1 = -INFINITY, mx2 = -INFINITY;
#pragma unroll
        for (int j = 0; j < 4; j++) {
            mx1 = fmaxf(mx1, fmaxf(sacc[j][0], sacc[j][1]));
            mx2 = fmaxf(mx2, fmaxf(sacc[j][2], sacc[j][3]));
        }
        mx1 = fmaxf(mx1, __shfl_xor_sync(0xffffffffu, mx1, 1));
        mx1 = fmaxf(mx1, __shfl_xor_sync(0xffffffffu, mx1, 2));
        mx2 = fmaxf(mx2, __shfl_xor_sync(0xffffffffu, mx2, 1));
        mx2 = fmaxf(mx2, __shfl_xor_sync(0xffffffffu, mx2, 2));

        const float mn1 = fmaxf(m1, mx1), mn2 = fmaxf(m2, mx2);
        const float sc1 = fast_exp(m1 - mn1), sc2 = fast_exp(m2 - mn2);
        float ls1 = 0.f, ls2 = 0.f;
#pragma unroll
        for (int j = 0; j < 4; j++) {
            sacc[j][0] = fast_exp(sacc[j][0] - mn1);
            sacc[j][1] = fast_exp(sacc[j][1] - mn1);
            sacc[j][2] = fast_exp(sacc[j][2] - mn2);
            sacc[j][3] = fast_exp(sacc[j][3] - mn2);
            ls1 += sacc[j][0] + sacc[j][1];
            ls2 += sacc[j][2] + sacc[j][3];
        }
        ls1 += __shfl_xor_sync(0xffffffffu, ls1, 1);
        ls1 += __shfl_xor_sync(0xffffffffu, ls1, 2);
        ls2 += __shfl_xor_sync(0xffffffffu, ls2, 1);
        ls2 += __shfl_xor_sync(0xffffffffu, ls2, 2);
        l1 = l1 * sc1 + ls1;  l2 = l2 * sc2 + ls2;
        m1 = mn1;             m2 = mn2;
#pragma unroll
        for (int t = 0; t < 16; t++) {
            ctx[t][0] *= sc1; ctx[t][1] *= sc1;
            ctx[t][2] *= sc2; ctx[t][3] *= sc2;
        }

        // ---- ctx += P V (1-term)
#pragma unroll
        for (int ks2 = 0; ks2 < 2; ks2++) {
            uint32_t pah[4];
            pah[0] = pack_f16(sacc[2 * ks2][0],     sacc[2 * ks2][1]);
            pah[1] = pack_f16(sacc[2 * ks2][2],     sacc[2 * ks2][3]);
            pah[2] = pack_f16(sacc[2 * ks2 + 1][0], sacc[2 * ks2 + 1][1]);
            pah[3] = pack_f16(sacc[2 * ks2 + 1][2], sacc[2 * ks2 + 1][3]);
#pragma unroll
            for (int p2 = 0; p2 < 8; p2++) {
                uint32_t vbh[4];
                const uint32_t vo =
                    (uint32_t)((ks2 * 16 + vRow) * ROWB + (p2 * 16 + vSel * 8) * 2);
                ldsm_x4_t(vbh, stb + 1 * ATILE + vo);
                mma_f16(ctx[2 * p2],     pah, vbh);
                mma_f16(ctx[2 * p2 + 1], pah, vbh + 2);
            }
        }
    }

    // ---- epilogue: normalize, fp16 ctx
    const float inv1 = 1.0f / l1, inv2 = 1.0f / l2;
    const size_t o1 = (size_t)(b * cS + row1) * cH + nh * cHD;
    const size_t o2 = (size_t)(b * cS + row2) * cH + nh * cHD;
#pragma unroll
    for (int t = 0; t < 16; t++) {
        const int d = t * 8 + tig * 2;
        *(uint32_t*)&g_ctx_hi[o1 + d] = pack_f16(ctx[t][0] * inv1, ctx[t][1] * inv1);
        *(uint32_t*)&g_ctx_hi[o2 + d] = pack_f16(ctx[t][2] * inv2, ctx[t][3] * inv2);
    }
}

// ---------------------------------------------------------------------------
// Launch
// ---------------------------------------------------------------------------
extern "C" void kernel_launch(void* const* d_in, const int* in_sizes, int n_in,
                              void* d_out, int out_size)
{
    (void)in_sizes; (void)n_in; (void)out_size;
    const float* hidden   = (const float*)d_in[0];
    const float* residual = (const float*)d_in[1];
    const float* alibi    = (const float*)d_in[2];
    const float* W_qkv    = (const float*)d_in[4];
    const float* b_qkv    = (const float*)d_in[5];
    const float* W_dense  = (const float*)d_in[6];
    const float* b_dense  = (const float*)d_in[7];
    float* out = (float*)d_out;

    cudaFuncSetAttribute(tc_gemm_1t<0>, cudaFuncAttributeMaxDynamicSharedMemorySize, SMEM_1T);
    cudaFuncSetAttribute(tc_gemm_1t<1>, cudaFuncAttributeMaxDynamicSharedMemorySize, SMEM_1T);
    cudaFuncSetAttribute(attn_mma,      cudaFuncAttributeMaxDynamicSharedMemorySize, ATTN_SMEM);

    __half *hid_hi, *wq_hi, *wd_hi, *cx_hi;
    cudaGetSymbolAddress((void**)&hid_hi, g_hid_hi);
    cudaGetSymbolAddress((void**)&wq_hi,  g_wqkv_hi);
    cudaGetSymbolAddress((void**)&wd_hi,  g_wd_hi);
    cudaGetSymbolAddress((void**)&cx_hi,  g_ctx_hi);

    // 0) fp32 -> fp16 (hi only, everywhere)
    split_fp32_hi<<<(cM * cH) / 1024, 256>>>((const float4*)hidden, (__half2*)hid_hi);
    split_fp32_hi<<<(cQKVN * cH) / 1024, 256>>>((const float4*)W_qkv, (__half2*)wq_hi);
    split_fp32_hi<<<(cH * cH) / 1024, 256>>>((const float4*)W_dense, (__half2*)wd_hi);

    // 1) QKV (single 1-term GEMM over all 12288 cols) -> q/k/v fp16
    tc_gemm_1t<0><<<dim3(cQKVN / GBN, cM / GBM), 256, SMEM_1T>>>(
        hid_hi, wq_hi, b_qkv, nullptr, nullptr);

    // 2) attention -> ctx fp16
    attn_mma<<<dim3(cS / ABQ, cB * cNH), 128, ATTN_SMEM>>>(alibi);

    // 3) dense (1-term) + bias + residual -> out
    tc_gemm_1t<1><<<dim3(cH / GBN, cM / GBM), 256, SMEM_1T>>>(
        cx_hi, wd_hi, b_dense, residual, out);
}